// round 7
// baseline (speedup 1.0000x reference)
#include <cuda_runtime.h>
#include <cuda_bf16.h>
#include <math.h>
#include <stdint.h>

#define NB   16
#define CIN  1024
#define CMID 256
#define C8   32
#define HH   48
#define WW   48
#define HW   (HH*WW)
#define NTOT (NB*HW)
#define OCH  512
#define NCLS 21
#define QKVC 384
#define NEG_INF (__int_as_float(0xff800000))

// ---------------- static scratch ----------------
__device__ float g_t0[NB*CMID*HW];
__device__ float g_cc[NB*CMID*HW];
__device__ float g_my[NB*CMID*HW];
__device__ float g_t1[NB*CMID*HW];
__device__ float g_qkv[(size_t)NB*QKVC*HW];
__device__ float g_h [NB*OCH*HW];
__device__ float g_stats[2*OCH];
__device__ float g_S[256];
__device__ float g_Wm[256];
__device__ float g_att[(size_t)NTOT*96];
__device__ float g_Bcc[QKVC];
__device__ float g_Bmy[QKVC];

__device__ __align__(256) __nv_bfloat16 g_XCh[(size_t)NTOT*1536];
__device__ __align__(256) __nv_bfloat16 g_XCl[(size_t)NTOT*1536];
__device__ __align__(256) __nv_bfloat16 g_ACTh[(size_t)NTOT*256];
__device__ __align__(256) __nv_bfloat16 g_ACTl[(size_t)NTOT*256];
__device__ __align__(256) __nv_bfloat16 g_WAh[256*9216],  g_WAl[256*9216];
__device__ __align__(256) __nv_bfloat16 g_WM1h[256*9216], g_WM1l[256*9216];
__device__ __align__(256) __nv_bfloat16 g_WBh[256*2304],  g_WBl[256*2304];
__device__ __align__(256) __nv_bfloat16 g_WM2h[256*2304], g_WM2l[256*2304];
__device__ __align__(256) __nv_bfloat16 g_WCh[512*13824], g_WCl[512*13824];
__device__ __align__(256) __nv_bfloat16 g_WQcch[QKVC*256], g_WQccl[QKVC*256];
__device__ __align__(256) __nv_bfloat16 g_WQmyh[QKVC*256], g_WQmyl[QKVC*256];

// ---------------- helpers ----------------
__device__ __forceinline__ uint32_t smem_u32(const void* p){
    uint32_t a;
    asm("{ .reg .u64 t; cvta.to.shared.u64 t, %1; cvt.u32.u64 %0, t; }" : "=r"(a) : "l"(p));
    return a;
}
__device__ __forceinline__ void cp16(uint32_t s, const void* g, uint32_t sz){
    asm volatile("cp.async.cg.shared.global [%0], [%1], 16, %2;" :: "r"(s), "l"(g), "r"(sz) : "memory");
}
__device__ __forceinline__ void ldmx4(uint32_t* r, uint32_t a){
    asm volatile("ldmatrix.sync.aligned.m8n8.x4.shared.b16 {%0,%1,%2,%3}, [%4];"
        : "=r"(r[0]),"=r"(r[1]),"=r"(r[2]),"=r"(r[3]) : "r"(a));
}
__device__ __forceinline__ void mma_bf16(float* d, const uint32_t* a, const uint32_t* b){
    asm volatile("mma.sync.aligned.m16n8k16.row.col.f32.bf16.bf16.f32 "
        "{%0,%1,%2,%3}, {%4,%5,%6,%7}, {%8,%9}, {%0,%1,%2,%3};"
        : "+f"(d[0]),"+f"(d[1]),"+f"(d[2]),"+f"(d[3])
        : "r"(a[0]),"r"(a[1]),"r"(a[2]),"r"(a[3]), "r"(b[0]),"r"(b[1]));
}

// ---------------- NCHW fp32 -> NHWC bf16 hi/lo ----------------
__global__ void to_nhwc_kernel(const float* __restrict__ src,
                               __nv_bfloat16* __restrict__ hi,
                               __nv_bfloat16* __restrict__ lo,
                               int C, int RS, int co)
{
    __shared__ float t[32][33];
    int hw0 = blockIdx.x * 32, c0 = blockIdx.y * 32, b = blockIdx.z;
    int lx = threadIdx.x, ly = threadIdx.y;
    for (int i = ly; i < 32; i += 8)
        t[i][lx] = src[((size_t)(b * C + c0 + i)) * HW + hw0 + lx];
    __syncthreads();
    for (int i = ly; i < 32; i += 8){
        float v = t[lx][i];
        __nv_bfloat16 h = __float2bfloat16(v);
        size_t o = ((size_t)(b * HW + hw0 + i)) * RS + co + c0 + lx;
        hi[o] = h;
        lo[o] = __float2bfloat16(v - __bfloat162float(h));
    }
}

__global__ void bn_to_nhwc_kernel(const float* __restrict__ src,
                                  const float* __restrict__ stats,
                                  __nv_bfloat16* __restrict__ hi,
                                  __nv_bfloat16* __restrict__ lo,
                                  int C, int RS, int co)
{
    __shared__ float t[32][33];
    int hw0 = blockIdx.x * 32, c0 = blockIdx.y * 32, b = blockIdx.z;
    int lx = threadIdx.x, ly = threadIdx.y;
    for (int i = ly; i < 32; i += 8){
        int c = c0 + i;
        float v = src[((size_t)(b * C + c)) * HW + hw0 + lx];
        t[i][lx] = fmaxf(fmaf(v, stats[2*c], stats[2*c+1]), 0.f);
    }
    __syncthreads();
    for (int i = ly; i < 32; i += 8){
        float v = t[lx][i];
        __nv_bfloat16 h = __float2bfloat16(v);
        size_t o = ((size_t)(b * HW + hw0 + i)) * RS + co + c0 + lx;
        hi[o] = h;
        lo[o] = __float2bfloat16(v - __bfloat162float(h));
    }
}

// ---------------- weight prep ----------------
__global__ void wprep_kernel(const float* __restrict__ w,
                             __nv_bfloat16* __restrict__ hi,
                             __nv_bfloat16* __restrict__ lo,
                             int M, int C, int ntaps)
{
    int i = blockIdx.x * 256 + threadIdx.x;
    int Kt = ntaps * C;
    if (i < M * Kt){
        int m = i / Kt; int rest = i - m * Kt; int t = rest / C; int c = rest - t * C;
        float v = w[(size_t)(m * C + c) * ntaps + t];
        __nv_bfloat16 h = __float2bfloat16(v);
        hi[i] = h;
        lo[i] = __float2bfloat16(v - __bfloat162float(h));
    }
}

// fused q(32)+k(32)+v(256) -> M=384 padded, 1x1, K=256; bias packed too
__global__ void wprep_qkv_kernel(const float* __restrict__ qw, const float* __restrict__ qb,
                                 const float* __restrict__ kw, const float* __restrict__ kb,
                                 const float* __restrict__ vw, const float* __restrict__ vb,
                                 __nv_bfloat16* __restrict__ hi, __nv_bfloat16* __restrict__ lo,
                                 float* __restrict__ bias)
{
    int i = blockIdx.x * 256 + threadIdx.x;
    if (i < QKVC * 256){
        int m = i >> 8, c = i & 255;
        float v = 0.f;
        if (m < 32)       v = qw[m * 256 + c];
        else if (m < 64)  v = kw[(m - 32) * 256 + c];
        else if (m < 320) v = vw[(m - 64) * 256 + c];
        __nv_bfloat16 h = __float2bfloat16(v);
        hi[i] = h;
        lo[i] = __float2bfloat16(v - __bfloat162float(h));
    }
    if (i < QKVC){
        float bv = 0.f;
        if (i < 32)       bv = qb[i];
        else if (i < 64)  bv = kb[i - 32];
        else if (i < 320) bv = vb[i - 64];
        bias[i] = bv;
    }
}

// ---------------- mma.sync implicit-GEMM conv (3-stage pipeline) ----------------
#define MC_BUF  40960
#define MC_SMEM (3*MC_BUF)   // 122880

struct McCtx {
    const __nv_bfloat16 *Ahi, *Alo, *Bhi, *Blo;
    int C, ntaps, Ktot, cpT, RS, co;
    int r, half, b, yy, xx, am;
    uint32_t sb;
};

__device__ __forceinline__ void mc_load(const McCtx& cx, int cc, int buf)
{
    int t   = cc / cx.cpT;
    int ci0 = (cc - t * cx.cpT) << 5;
    uint32_t dst = cx.sb + buf * MC_BUF + cx.r * 80 + cx.half * 32;
    {
        size_t off = (size_t)cx.am * cx.Ktot + t * cx.C + ci0 + cx.half * 16;
        cp16(dst,              cx.Ahi + off,     16);
        cp16(dst + 16,         cx.Ahi + off + 8, 16);
        cp16(dst + 10240,      cx.Alo + off,     16);
        cp16(dst + 10240 + 16, cx.Alo + off + 8, 16);
    }
    {
        int dy = 0, dx = 0;
        if (cx.ntaps == 9){ dy = t / 3 - 1; dx = t - (t / 3) * 3 - 1; }
        int ys = cx.yy + dy, xs = cx.xx + dx;
        bool bv = (ys >= 0 && ys < HH && xs >= 0 && xs < WW);
        size_t off = bv ? ((size_t)(cx.b * HW + ys * WW + xs) * cx.RS + cx.co + ci0 + cx.half * 16) : 0;
        uint32_t sz = bv ? 16u : 0u;
        cp16(dst + 20480,      cx.Bhi + off,     sz);
        cp16(dst + 20480 + 16, cx.Bhi + off + 8, sz);
        cp16(dst + 30720,      cx.Blo + off,     sz);
        cp16(dst + 30720 + 16, cx.Blo + off + 8, sz);
    }
}

__global__ __launch_bounds__(256) void mma_conv_kernel(
    const __nv_bfloat16* __restrict__ Ahi, const __nv_bfloat16* __restrict__ Alo,
    const __nv_bfloat16* __restrict__ Bhi, const __nv_bfloat16* __restrict__ Blo,
    int M, int C, int ntaps, int RS, int co,
    const float* __restrict__ bias,
    float* __restrict__ out)
{
    extern __shared__ char dynsm[];
    const int tid = threadIdx.x, lane = tid & 31, wid = tid >> 5;
    const int wm = wid & 1, wn = wid >> 1;
    const int m0 = blockIdx.y * 128;
    const int n0 = blockIdx.x * 128;

    McCtx cx;
    cx.Ahi = Ahi; cx.Alo = Alo; cx.Bhi = Bhi; cx.Blo = Blo;
    cx.C = C; cx.ntaps = ntaps; cx.Ktot = ntaps * C; cx.cpT = C >> 5;
    cx.RS = RS; cx.co = co;
    cx.r = tid >> 1; cx.half = tid & 1;
    {
        int n = n0 + cx.r;
        cx.b = n / HW;
        int hw = n - cx.b * HW;
        cx.yy = hw / WW;
        cx.xx = hw - cx.yy * WW;
    }
    cx.am = m0 + cx.r;
    cx.sb = smem_u32(dynsm);

    float acc[4][4][4];
#pragma unroll
    for (int i = 0; i < 4; i++)
#pragma unroll
        for (int j = 0; j < 4; j++)
#pragma unroll
            for (int q = 0; q < 4; q++) acc[i][j][q] = 0.f;

    const int NC = cx.Ktot >> 5;

    mc_load(cx, 0, 0);
    asm volatile("cp.async.commit_group;" ::: "memory");
    if (NC > 1){
        mc_load(cx, 1, 1);
        asm volatile("cp.async.commit_group;" ::: "memory");
    }

    const uint32_t aRowOff = (uint32_t)(lane & 15) * 80;
    const uint32_t aColOff = (uint32_t)(lane >> 4) * 16;
    const uint32_t bRowOff = (uint32_t)((lane & 7) + ((lane >> 4) << 3)) * 80;
    const uint32_t bColOff = (uint32_t)((lane >> 3) & 1) * 16;

    int bufc = 0;
    for (int cc = 0; cc < NC; cc++){
        if (cc + 1 < NC){
            asm volatile("cp.async.wait_group 1;" ::: "memory");
        } else {
            asm volatile("cp.async.wait_group 0;" ::: "memory");
        }
        __syncthreads();
        if (cc + 2 < NC){
            int nb = bufc + 2; if (nb >= 3) nb -= 3;
            mc_load(cx, cc + 2, nb);
            asm volatile("cp.async.commit_group;" ::: "memory");
        }
        uint32_t base = cx.sb + bufc * MC_BUF;
#pragma unroll
        for (int k16 = 0; k16 < 2; k16++){
            uint32_t ac = (uint32_t)k16 * 32 + aColOff;
            uint32_t bc = (uint32_t)k16 * 32 + bColOff;
            uint32_t ah[4][4], al[4][4], bh[2][4], bl[2][4];
#pragma unroll
            for (int mi = 0; mi < 4; mi++){
                uint32_t ad = base + (uint32_t)(wm * 64 + mi * 16) * 80 + aRowOff + ac;
                ldmx4(ah[mi], ad);
                ldmx4(al[mi], ad + 10240);
            }
#pragma unroll
            for (int ng = 0; ng < 2; ng++){
                uint32_t bd = base + 20480 + (uint32_t)(wn * 32 + ng * 16) * 80 + bRowOff + bc;
                ldmx4(bh[ng], bd);
                ldmx4(bl[ng], bd + 10240);
            }
#pragma unroll
            for (int mi = 0; mi < 4; mi++){
#pragma unroll
                for (int ni = 0; ni < 4; ni++){
                    const uint32_t* bhp = &bh[ni >> 1][(ni & 1) * 2];
                    const uint32_t* blp = &bl[ni >> 1][(ni & 1) * 2];
                    mma_bf16(acc[mi][ni], ah[mi], bhp);
                    mma_bf16(acc[mi][ni], ah[mi], blp);
                    mma_bf16(acc[mi][ni], al[mi], bhp);
                }
            }
        }
        bufc++; if (bufc == 3) bufc = 0;
    }

    int tb = n0 / HW;
    int hw0 = n0 - tb * HW;
#pragma unroll
    for (int mi = 0; mi < 4; mi++){
        int mrow = m0 + wm * 64 + mi * 16 + (lane >> 2);
        float b0 = bias ? __ldg(bias + mrow)     : 0.f;
        float b1 = bias ? __ldg(bias + mrow + 8) : 0.f;
#pragma unroll
        for (int ni = 0; ni < 4; ni++){
            int col = hw0 + wn * 32 + ni * 8 + (lane & 3) * 2;
            float2 v0 = make_float2(acc[mi][ni][0] + b0, acc[mi][ni][1] + b0);
            float2 v1 = make_float2(acc[mi][ni][2] + b1, acc[mi][ni][3] + b1);
            *(float2*)&out[((size_t)(tb * M + mrow)) * HW + col]     = v0;
            *(float2*)&out[((size_t)(tb * M + mrow + 8)) * HW + col] = v1;
        }
    }
}

// ---------------- fp32 GEMM (classifier only) ----------------
__global__ __launch_bounds__(256) void gemm_conv_kernel(
    const float* __restrict__ Wt, const float* __restrict__ p0,
    int M, int Cin, const float* __restrict__ bias, float* __restrict__ out)
{
    __shared__ float As[16][128];
    __shared__ float Bs[16][128];
    const int tid = threadIdx.x;
    const int tx = tid & 15, ty = tid >> 4;
    const int m0 = blockIdx.y * 128;
    const int n0 = blockIdx.x * 128;
    float acc[8][8];
#pragma unroll
    for (int i = 0; i < 8; i++)
#pragma unroll
        for (int j = 0; j < 8; j++) acc[i][j] = 0.f;
    const int nl = tid & 127;
    const int nglob = n0 + nl;
    const int bb = nglob / HW;
    const int hw = nglob - bb * HW;
    const int kbB = (tid >> 7) * 8;
    const int ml = tid >> 1;
    const int kbA = (tid & 1) * 8;
    for (int k0 = 0; k0 < Cin; k0 += 16){
        int m = m0 + ml;
        const float* wp = Wt + (size_t)m * Cin + (k0 + kbA);
#pragma unroll
        for (int i = 0; i < 8; i++)
            As[kbA + i][ml] = (m < M) ? wp[i] : 0.f;
#pragma unroll
        for (int i = 0; i < 8; i++)
            Bs[kbB + i][nl] = p0[((size_t)(bb * Cin + k0 + kbB + i)) * HW + hw];
        __syncthreads();
#pragma unroll
        for (int kk = 0; kk < 16; kk++){
            float a[8], bq[8];
#pragma unroll
            for (int i = 0; i < 8; i++) a[i]  = As[kk][ty + 16 * i];
#pragma unroll
            for (int j = 0; j < 8; j++) bq[j] = Bs[kk][tx + 16 * j];
#pragma unroll
            for (int i = 0; i < 8; i++)
#pragma unroll
                for (int j = 0; j < 8; j++)
                    acc[i][j] = fmaf(a[i], bq[j], acc[i][j]);
        }
        __syncthreads();
    }
#pragma unroll
    for (int i = 0; i < 8; i++){
        int m = m0 + ty + 16 * i;
        if (m >= M) continue;
        float bval = bias ? bias[m] : 0.f;
#pragma unroll
        for (int j = 0; j < 8; j++){
            int n = n0 + tx + 16 * j;
            int b = n / HW;
            int hw2 = n - b * HW;
            out[((size_t)(b * M + m)) * HW + hw2] = acc[i][j] + bval;
        }
    }
}

// ---------------- BatchNorm ----------------
__global__ void bn_stats_kernel(const float* __restrict__ x,
                                const float* __restrict__ g,
                                const float* __restrict__ bta,
                                float* __restrict__ stats, int C)
{
    int c = blockIdx.x, tid = threadIdx.x;
    float s = 0.f, sq = 0.f;
    for (int i = tid; i < NB * HW; i += 256){
        int bb = i / HW;
        float v = x[((size_t)(bb * C + c)) * HW + (i - bb * HW)];
        s += v; sq += v * v;
    }
    __shared__ float sh1[256], sh2[256];
    sh1[tid] = s; sh2[tid] = sq;
    __syncthreads();
    for (int st = 128; st; st >>= 1){
        if (tid < st){ sh1[tid] += sh1[tid + st]; sh2[tid] += sh2[tid + st]; }
        __syncthreads();
    }
    if (tid == 0){
        float n = (float)(NB * HW);
        float m = sh1[0] / n;
        float var = sh2[0] / n - m * m;
        float sc = g[c] * rsqrtf(var + 1e-5f);
        stats[2 * c] = sc;
        stats[2 * c + 1] = bta[c] - m * sc;
    }
}

__global__ void bn_apply_kernel(const float* __restrict__ x,
                                const float* __restrict__ stats,
                                float* __restrict__ y, int C, int total)
{
    int i = blockIdx.x * 256 + threadIdx.x;
    if (i < total){
        int c = (i / HW) % C;
        y[i] = fmaxf(fmaf(x[i], stats[2 * c], stats[2 * c + 1]), 0.f);
    }
}

// ---------------- criss-cross attention (qkv buffer, channel stride QKVC) ----
__global__ void cc_logits_col_kernel(const float* __restrict__ qkv,
                                     float* __restrict__ att)
{
    int w = blockIdx.x, b = blockIdx.y, tid = threadIdx.x;
    __shared__ float qs[32][48], ks[32][48];
    for (int i = tid; i < 32 * 48; i += 256){
        int c = i / 48, h = i - (i / 48) * 48;
        qs[c][h] = qkv[((size_t)((b * QKVC + c) * 48 + h)) * 48 + w];
        ks[c][h] = qkv[((size_t)((b * QKVC + 32 + c) * 48 + h)) * 48 + w];
    }
    __syncthreads();
    for (int i = tid; i < 48 * 48; i += 256){
        int h = i / 48, g = i - (i / 48) * 48;
        float s;
        if (g == h) s = NEG_INF;
        else {
            s = 0.f;
#pragma unroll
            for (int c = 0; c < 32; c++) s += qs[c][h] * ks[c][g];
        }
        att[((size_t)((b * 48 + h) * 48 + w)) * 96 + g] = s;
    }
}

__global__ void cc_logits_row_kernel(const float* __restrict__ qkv,
                                     float* __restrict__ att)
{
    int h = blockIdx.x, b = blockIdx.y, tid = threadIdx.x;
    __shared__ float qs[32][48], ks[32][48];
    for (int i = tid; i < 32 * 48; i += 256){
        int c = i / 48, w = i - (i / 48) * 48;
        qs[c][w] = qkv[((size_t)((b * QKVC + c) * 48 + h)) * 48 + w];
        ks[c][w] = qkv[((size_t)((b * QKVC + 32 + c) * 48 + h)) * 48 + w];
    }
    __syncthreads();
    for (int i = tid; i < 48 * 48; i += 256){
        int w = i / 48, v2 = i - (i / 48) * 48;
        float s = 0.f;
#pragma unroll
        for (int c = 0; c < 32; c++) s += qs[c][w] * ks[c][v2];
        att[((size_t)((b * 48 + h) * 48 + w)) * 96 + 48 + v2] = s;
    }
}

__global__ void cc_softmax_kernel(float* __restrict__ att)
{
    int row  = blockIdx.x * 8 + (threadIdx.x >> 5);
    int lane = threadIdx.x & 31;
    float* p = att + (size_t)row * 96;
    float v0 = p[lane], v1 = p[lane + 32], v2 = p[lane + 64];
    float mx = fmaxf(v0, fmaxf(v1, v2));
#pragma unroll
    for (int off = 16; off; off >>= 1) mx = fmaxf(mx, __shfl_xor_sync(0xffffffff, mx, off));
    float e0 = expf(v0 - mx), e1 = expf(v1 - mx), e2 = expf(v2 - mx);
    float s = e0 + e1 + e2;
#pragma unroll
    for (int off = 16; off; off >>= 1) s += __shfl_xor_sync(0xffffffff, s, off);
    float inv = 1.f / s;
    p[lane] = e0 * inv; p[lane + 32] = e1 * inv; p[lane + 64] = e2 * inv;
}

#define CC_SMEM ((256*48 + 48*48) * 4)

__global__ void cc_out_col_kernel(const float* __restrict__ qkv,
                                  const float* __restrict__ att,
                                  const float* __restrict__ xin,
                                  const float* __restrict__ gamma,
                                  float* __restrict__ out)
{
    extern __shared__ float cs[];
    float* vs = cs; float* as = cs + 256 * 48;
    int w = blockIdx.x, b = blockIdx.y, tid = threadIdx.x;
    for (int i = tid; i < 256 * 48; i += 256){
        int c = i / 48, g = i - (i / 48) * 48;
        vs[i] = qkv[((size_t)((b * QKVC + 64 + c) * 48 + g)) * 48 + w];
    }
    for (int i = tid; i < 48 * 48; i += 256){
        int h = i / 48, g = i - (i / 48) * 48;
        as[i] = att[((size_t)((b * 48 + h) * 48 + w)) * 96 + g];
    }
    __syncthreads();
    float gm = gamma[0];
    for (int i = tid; i < 256 * 48; i += 256){
        int c = i / 48, h = i - (i / 48) * 48;
        float s = 0.f;
#pragma unroll
        for (int g = 0; g < 48; g++) s += vs[c * 48 + g] * as[h * 48 + g];
        size_t o = ((size_t)((b * 256 + c) * 48 + h)) * 48 + w;
        out[o] = xin[o] + gm * s;
    }
}

__global__ void cc_out_row_kernel(const float* __restrict__ qkv,
                                  const float* __restrict__ att,
                                  const float* __restrict__ gamma,
                                  float* __restrict__ out)
{
    extern __shared__ float cs[];
    float* vs = cs; float* as = cs + 256 * 48;
    int h = blockIdx.x, b = blockIdx.y, tid = threadIdx.x;
    for (int i = tid; i < 256 * 48; i += 256){
        vs[i] = qkv[((size_t)(b * QKVC + 64 + i / 48) * 48 + h) * 48 + (i % 48)];
    }
    for (int i = tid; i < 48 * 48; i += 256){
        int w2 = i / 48, v2 = i - (i / 48) * 48;
        as[i] = att[((size_t)((b * 48 + h) * 48 + w2)) * 96 + 48 + v2];
    }
    __syncthreads();
    float gm = gamma[0];
    for (int i = tid; i < 256 * 48; i += 256){
        int c = i / 48, w2 = i - (i / 48) * 48;
        float s = 0.f;
#pragma unroll
        for (int v2 = 0; v2 < 48; v2++) s += vs[c * 48 + v2] * as[w2 * 48 + v2];
        size_t o = ((size_t)((b * 256 + c) * 48 + h)) * 48 + w2;
        out[o] += gm * s;
    }
}

// ---------------- grid attention (qkv buffer) ----------------
__global__ void gram_kernel(const float* __restrict__ qkv,
                            float* __restrict__ S)
{
    int b1 = blockIdx.x >> 4, b2 = blockIdx.x & 15;
    const float* qp = qkv + (size_t)b1 * (QKVC * HW);
    const float* kp = qkv + (size_t)b2 * (QKVC * HW) + 32 * HW;
    int tid = threadIdx.x;
    float s = 0.f;
    for (int i = tid; i < C8 * HW; i += 256) s += qp[i] * kp[i];
    __shared__ float sh[256];
    sh[tid] = s;
    __syncthreads();
    for (int st = 128; st; st >>= 1){
        if (tid < st) sh[tid] += sh[tid + st];
        __syncthreads();
    }
    if (tid == 0) S[blockIdx.x] = sh[0];
}

__global__ void myw_kernel(const float* __restrict__ S, float* __restrict__ Wm)
{
    int b1 = threadIdx.x;
    if (b1 < 16){
        int gh = b1 >> 2, gw = b1 & 3;
        float l[8];
        for (int j = 0; j < 4; j++){
            int b2 = j * 4 + gw;
            l[j] = (j == gh) ? NEG_INF : S[b1 * 16 + b2];
        }
        for (int j = 0; j < 4; j++) l[4 + j] = S[b1 * 16 + gh * 4 + j];
        float mx = NEG_INF;
        for (int j = 0; j < 8; j++) mx = fmaxf(mx, l[j]);
        float sm = 0.f;
        for (int j = 0; j < 8; j++){ l[j] = expf(l[j] - mx); sm += l[j]; }
        float inv = 1.f / sm;
        float w[16];
        for (int i = 0; i < 16; i++) w[i] = 0.f;
        for (int j = 0; j < 4; j++) w[j * 4 + gw] += l[j] * inv;
        for (int j = 0; j < 4; j++) w[gh * 4 + j] += l[4 + j] * inv;
        for (int i = 0; i < 16; i++) Wm[b1 * 16 + i] = w[i];
    }
}

__global__ void my_combine_kernel(const float* __restrict__ qkv,
                                  const float* __restrict__ Wm,
                                  const float* __restrict__ xin,
                                  const float* __restrict__ gamma,
                                  float* __restrict__ out)
{
    __shared__ float ws[256];
    if (threadIdx.x < 256) ws[threadIdx.x] = Wm[threadIdx.x];
    __syncthreads();
    const int PB = CMID * HW;
    int n = blockIdx.x * 256 + threadIdx.x;
    if (n < PB){
        float vv[16];
#pragma unroll
        for (int b = 0; b < 16; b++)
            vv[b] = qkv[(size_t)b * (QKVC * HW) + 64 * HW + n];
        float gm = gamma[0];
#pragma unroll
        for (int b1 = 0; b1 < 16; b1++){
            float o = 0.f;
#pragma unroll
            for (int b2 = 0; b2 < 16; b2++) o += ws[b1 * 16 + b2] * vv[b2];
            out[(size_t)b1 * PB + n] = gm * o + xin[(size_t)b1 * PB + n];
        }
    }
}

// ---------------- host ----------------
extern "C" void kernel_launch(void* const* d_in, const int* in_sizes, int n_in,
                              void* d_out, int out_size)
{
    const float* x      = (const float*)d_in[0];
    const float* w_a    = (const float*)d_in[1];
    const float* g_a    = (const float*)d_in[2];
    const float* b_a    = (const float*)d_in[3];
    const float* ccq_w  = (const float*)d_in[4];
    const float* ccq_b  = (const float*)d_in[5];
    const float* cck_w  = (const float*)d_in[6];
    const float* cck_b  = (const float*)d_in[7];
    const float* ccv_w  = (const float*)d_in[8];
    const float* ccv_b  = (const float*)d_in[9];
    const float* cc_gm  = (const float*)d_in[10];
    const float* w_b    = (const float*)d_in[11];
    const float* g_b    = (const float*)d_in[12];
    const float* b_b    = (const float*)d_in[13];
    const float* w_m1   = (const float*)d_in[14];
    const float* g_m1   = (const float*)d_in[15];
    const float* b_m1   = (const float*)d_in[16];
    const float* myq_w  = (const float*)d_in[17];
    const float* myq_b  = (const float*)d_in[18];
    const float* myk_w  = (const float*)d_in[19];
    const float* myk_b  = (const float*)d_in[20];
    const float* myv_w  = (const float*)d_in[21];
    const float* myv_b  = (const float*)d_in[22];
    const float* my_gm  = (const float*)d_in[23];
    const float* w_m2   = (const float*)d_in[24];
    const float* g_m2   = (const float*)d_in[25];
    const float* b_m2   = (const float*)d_in[26];
    const float* w_c    = (const float*)d_in[27];
    const float* g_c    = (const float*)d_in[28];
    const float* b_c    = (const float*)d_in[29];
    const float* w_cls  = (const float*)d_in[30];
    const float* b_cls  = (const float*)d_in[31];

    cudaFuncSetAttribute(mma_conv_kernel, cudaFuncAttributeMaxDynamicSharedMemorySize, MC_SMEM);
    cudaFuncSetAttribute(cc_out_col_kernel, cudaFuncAttributeMaxDynamicSharedMemorySize, CC_SMEM);
    cudaFuncSetAttribute(cc_out_row_kernel, cudaFuncAttributeMaxDynamicSharedMemorySize, CC_SMEM);

    float *pt0, *pcc, *pmy, *pt1, *pqkv, *ph, *pst, *pS, *pWm, *patt, *pBcc, *pBmy;
    cudaGetSymbolAddress((void**)&pt0, g_t0);
    cudaGetSymbolAddress((void**)&pcc, g_cc);
    cudaGetSymbolAddress((void**)&pmy, g_my);
    cudaGetSymbolAddress((void**)&pt1, g_t1);
    cudaGetSymbolAddress((void**)&pqkv, g_qkv);
    cudaGetSymbolAddress((void**)&ph,  g_h);
    cudaGetSymbolAddress((void**)&pst, g_stats);
    cudaGetSymbolAddress((void**)&pS,  g_S);
    cudaGetSymbolAddress((void**)&pWm, g_Wm);
    cudaGetSymbolAddress((void**)&patt, g_att);
    cudaGetSymbolAddress((void**)&pBcc, g_Bcc);
    cudaGetSymbolAddress((void**)&pBmy, g_Bmy);

    __nv_bfloat16 *XCh,*XCl,*ACTh,*ACTl;
    __nv_bfloat16 *WAh,*WAl,*WM1h,*WM1l,*WBh,*WBl,*WM2h,*WM2l,*WCh,*WCl;
    __nv_bfloat16 *WQcch,*WQccl,*WQmyh,*WQmyl;
    cudaGetSymbolAddress((void**)&XCh, g_XCh);   cudaGetSymbolAddress((void**)&XCl, g_XCl);
    cudaGetSymbolAddress((void**)&ACTh, g_ACTh); cudaGetSymbolAddress((void**)&ACTl, g_ACTl);
    cudaGetSymbolAddress((void**)&WAh, g_WAh);   cudaGetSymbolAddress((void**)&WAl, g_WAl);
    cudaGetSymbolAddress((void**)&WM1h, g_WM1h); cudaGetSymbolAddress((void**)&WM1l, g_WM1l);
    cudaGetSymbolAddress((void**)&WBh, g_WBh);   cudaGetSymbolAddress((void**)&WBl, g_WBl);
    cudaGetSymbolAddress((void**)&WM2h, g_WM2h); cudaGetSymbolAddress((void**)&WM2l, g_WM2l);
    cudaGetSymbolAddress((void**)&WCh, g_WCh);   cudaGetSymbolAddress((void**)&WCl, g_WCl);
    cudaGetSymbolAddress((void**)&WQcch, g_WQcch); cudaGetSymbolAddress((void**)&WQccl, g_WQccl);
    cudaGetSymbolAddress((void**)&WQmyh, g_WQmyh); cudaGetSymbolAddress((void**)&WQmyl, g_WQmyl);

    const dim3 blk(256);
    const dim3 tr_blk(32, 8);
    const int NT = NTOT / 128;
    const int TOT_MID = NB*CMID*HW;

    // weight prep
    wprep_kernel<<<(256*9216 + 255)/256, blk>>>(w_a,  WAh,  WAl,  256, 1024, 9);
    wprep_kernel<<<(256*9216 + 255)/256, blk>>>(w_m1, WM1h, WM1l, 256, 1024, 9);
    wprep_kernel<<<(256*2304 + 255)/256, blk>>>(w_b,  WBh,  WBl,  256, 256, 9);
    wprep_kernel<<<(256*2304 + 255)/256, blk>>>(w_m2, WM2h, WM2l, 256, 256, 9);
    wprep_kernel<<<(512*13824 + 255)/256, blk>>>(w_c, WCh,  WCl,  512, 1536, 9);
    wprep_qkv_kernel<<<(QKVC*256 + 255)/256, blk>>>(ccq_w, ccq_b, cck_w, cck_b, ccv_w, ccv_b,
                                                    WQcch, WQccl, pBcc);
    wprep_qkv_kernel<<<(QKVC*256 + 255)/256, blk>>>(myq_w, myq_b, myk_w, myk_b, myv_w, myv_b,
                                                    WQmyh, WQmyl, pBmy);

    // x -> XC[0:1024]
    to_nhwc_kernel<<<dim3(HW/32, 1024/32, NB), tr_blk>>>(x, XCh, XCl, 1024, 1536, 0);

    // conv_a, conv_m1
    mma_conv_kernel<<<dim3(NT, 2), blk, MC_SMEM>>>(WAh, WAl, XCh, XCl, 256, 1024, 9, 1536, 0, nullptr, pt0);
    bn_stats_kernel<<<CMID, blk>>>(pt0, g_a, b_a, pst, CMID);
    bn_apply_kernel<<<(TOT_MID + 255)/256, blk>>>(pt0, pst, pcc, CMID, TOT_MID);

    mma_conv_kernel<<<dim3(NT, 2), blk, MC_SMEM>>>(WM1h, WM1l, XCh, XCl, 256, 1024, 9, 1536, 0, nullptr, pt0);
    bn_stats_kernel<<<CMID, blk>>>(pt0, g_m1, b_m1, pst, CMID);
    bn_apply_kernel<<<(TOT_MID + 255)/256, blk>>>(pt0, pst, pmy, CMID, TOT_MID);

    // cc attention x2
    {
        float* ca = pcc; float* cb = pt1;
        for (int it = 0; it < 2; it++){
            to_nhwc_kernel<<<dim3(HW/32, 256/32, NB), tr_blk>>>(ca, ACTh, ACTl, 256, 256, 0);
            mma_conv_kernel<<<dim3(NT, 3), blk, MC_SMEM>>>(WQcch, WQccl, ACTh, ACTl,
                                                           QKVC, 256, 1, 256, 0, pBcc, pqkv);
            cc_logits_col_kernel<<<dim3(WW, NB), blk>>>(pqkv, patt);
            cc_logits_row_kernel<<<dim3(HH, NB), blk>>>(pqkv, patt);
            cc_softmax_kernel<<<NTOT/8, blk>>>(patt);
            cc_out_col_kernel<<<dim3(WW, NB), blk, CC_SMEM>>>(pqkv, patt, ca, cc_gm, cb);
            cc_out_row_kernel<<<dim3(HH, NB), blk, CC_SMEM>>>(pqkv, patt, cc_gm, cb);
            float* tmp = ca; ca = cb; cb = tmp;
        }
    }

    // my attention x2
    {
        float* ma = pmy; float* mb = pt1;
        for (int it = 0; it < 2; it++){
            to_nhwc_kernel<<<dim3(HW/32, 256/32, NB), tr_blk>>>(ma, ACTh, ACTl, 256, 256, 0);
            mma_conv_kernel<<<dim3(NT, 3), blk, MC_SMEM>>>(WQmyh, WQmyl, ACTh, ACTl,
                                                           QKVC, 256, 1, 256, 0, pBmy, pqkv);
            gram_kernel<<<256, blk>>>(pqkv, pS);
            myw_kernel<<<1, 32>>>(pS, pWm);
            my_combine_kernel<<<(CMID*HW + 255)/256, blk>>>(pqkv, pWm, ma, my_gm, mb);
            float* tmp = ma; ma = mb; mb = tmp;
        }
    }

    // conv_b: input pcc -> BN -> XC@1024 (fused)
    to_nhwc_kernel<<<dim3(HW/32, 256/32, NB), tr_blk>>>(pcc, ACTh, ACTl, 256, 256, 0);
    mma_conv_kernel<<<dim3(NT, 2), blk, MC_SMEM>>>(WBh, WBl, ACTh, ACTl, 256, 256, 9, 256, 0, nullptr, pt0);
    bn_stats_kernel<<<CMID, blk>>>(pt0, g_b, b_b, pst, CMID);
    bn_to_nhwc_kernel<<<dim3(HW/32, 256/32, NB), tr_blk>>>(pt0, pst, XCh, XCl, 256, 1536, 1024);

    // conv_m2: input pmy -> BN -> XC@1280 (fused)
    to_nhwc_kernel<<<dim3(HW/32, 256/32, NB), tr_blk>>>(pmy, ACTh, ACTl, 256, 256, 0);
    mma_conv_kernel<<<dim3(NT, 2), blk, MC_SMEM>>>(WM2h, WM2l, ACTh, ACTl, 256, 256, 9, 256, 0, nullptr, pt0);
    bn_stats_kernel<<<CMID, blk>>>(pt0, g_m2, b_m2, pst, CMID);
    bn_to_nhwc_kernel<<<dim3(HW/32, 256/32, NB), tr_blk>>>(pt0, pst, XCh, XCl, 256, 1536, 1280);

    // conv_c + BN
    mma_conv_kernel<<<dim3(NT, 4), blk, MC_SMEM>>>(WCh, WCl, XCh, XCl, 512, 1536, 9, 1536, 0, nullptr, ph);
    bn_stats_kernel<<<OCH, blk>>>(ph, g_c, b_c, pst, OCH);
    bn_apply_kernel<<<(NB*OCH*HW + 255)/256, blk>>>(ph, pst, ph, OCH, NB*OCH*HW);

    // classifier
    gemm_conv_kernel<<<dim3(NT, 1), blk>>>(w_cls, ph, NCLS, OCH, b_cls, (float*)d_out);
}

// round 8
// speedup vs baseline: 1.1839x; 1.1839x over previous
#include <cuda_runtime.h>
#include <cuda_bf16.h>
#include <math.h>
#include <stdint.h>

#define NB   16
#define CIN  1024
#define CMID 256
#define C8   32
#define HH   48
#define WW   48
#define HW   (HH*WW)
#define NTOT (NB*HW)
#define OCH  512
#define NCLS 21
#define QKVC 384
#define NEG_INF (__int_as_float(0xff800000))

// ---------------- static scratch ----------------
__device__ float g_t0[NB*CMID*HW];
__device__ float g_cc[NB*CMID*HW];
__device__ float g_my[NB*CMID*HW];
__device__ float g_t1[NB*CMID*HW];
__device__ float g_qkv[(size_t)NB*QKVC*HW];
__device__ float g_h [NB*OCH*HW];
__device__ float g_stats[2*OCH];
__device__ float g_S[256];
__device__ float g_Wm[256];
__device__ float g_att[(size_t)NTOT*96];
__device__ float g_Bcc[QKVC];
__device__ float g_Bmy[QKVC];

__device__ __align__(256) __nv_bfloat16 g_XCh[(size_t)NTOT*1536];
__device__ __align__(256) __nv_bfloat16 g_XCl[(size_t)NTOT*1536];
__device__ __align__(256) __nv_bfloat16 g_ACTh[(size_t)NTOT*256];
__device__ __align__(256) __nv_bfloat16 g_ACTl[(size_t)NTOT*256];
__device__ __align__(256) __nv_bfloat16 g_WAh[256*9216],  g_WAl[256*9216];
__device__ __align__(256) __nv_bfloat16 g_WM1h[256*9216], g_WM1l[256*9216];
__device__ __align__(256) __nv_bfloat16 g_WBh[256*2304],  g_WBl[256*2304];
__device__ __align__(256) __nv_bfloat16 g_WM2h[256*2304], g_WM2l[256*2304];
__device__ __align__(256) __nv_bfloat16 g_WCh[512*13824], g_WCl[512*13824];
__device__ __align__(256) __nv_bfloat16 g_WQcch[QKVC*256], g_WQccl[QKVC*256];
__device__ __align__(256) __nv_bfloat16 g_WQmyh[QKVC*256], g_WQmyl[QKVC*256];

// ---------------- helpers ----------------
__device__ __forceinline__ uint32_t smem_u32(const void* p){
    uint32_t a;
    asm("{ .reg .u64 t; cvta.to.shared.u64 t, %1; cvt.u32.u64 %0, t; }" : "=r"(a) : "l"(p));
    return a;
}
__device__ __forceinline__ void cp16(uint32_t s, const void* g, uint32_t sz){
    asm volatile("cp.async.cg.shared.global [%0], [%1], 16, %2;" :: "r"(s), "l"(g), "r"(sz) : "memory");
}
__device__ __forceinline__ void ldmx4(uint32_t* r, uint32_t a){
    asm volatile("ldmatrix.sync.aligned.m8n8.x4.shared.b16 {%0,%1,%2,%3}, [%4];"
        : "=r"(r[0]),"=r"(r[1]),"=r"(r[2]),"=r"(r[3]) : "r"(a));
}
__device__ __forceinline__ void mma_bf16(float* d, const uint32_t* a, const uint32_t* b){
    asm volatile("mma.sync.aligned.m16n8k16.row.col.f32.bf16.bf16.f32 "
        "{%0,%1,%2,%3}, {%4,%5,%6,%7}, {%8,%9}, {%0,%1,%2,%3};"
        : "+f"(d[0]),"+f"(d[1]),"+f"(d[2]),"+f"(d[3])
        : "r"(a[0]),"r"(a[1]),"r"(a[2]),"r"(a[3]), "r"(b[0]),"r"(b[1]));
}

// ---------------- NCHW fp32 -> NHWC bf16 hi/lo ----------------
__global__ void to_nhwc_kernel(const float* __restrict__ src,
                               __nv_bfloat16* __restrict__ hi,
                               __nv_bfloat16* __restrict__ lo,
                               int C, int RS, int co)
{
    __shared__ float t[32][33];
    int hw0 = blockIdx.x * 32, c0 = blockIdx.y * 32, b = blockIdx.z;
    int lx = threadIdx.x, ly = threadIdx.y;
    for (int i = ly; i < 32; i += 8)
        t[i][lx] = src[((size_t)(b * C + c0 + i)) * HW + hw0 + lx];
    __syncthreads();
    for (int i = ly; i < 32; i += 8){
        float v = t[lx][i];
        __nv_bfloat16 h = __float2bfloat16(v);
        size_t o = ((size_t)(b * HW + hw0 + i)) * RS + co + c0 + lx;
        hi[o] = h;
        lo[o] = __float2bfloat16(v - __bfloat162float(h));
    }
}

__global__ void bn_to_nhwc_kernel(const float* __restrict__ src,
                                  const float* __restrict__ stats,
                                  __nv_bfloat16* __restrict__ hi,
                                  __nv_bfloat16* __restrict__ lo,
                                  int C, int RS, int co)
{
    __shared__ float t[32][33];
    int hw0 = blockIdx.x * 32, c0 = blockIdx.y * 32, b = blockIdx.z;
    int lx = threadIdx.x, ly = threadIdx.y;
    for (int i = ly; i < 32; i += 8){
        int c = c0 + i;
        float v = src[((size_t)(b * C + c)) * HW + hw0 + lx];
        t[i][lx] = fmaxf(fmaf(v, stats[2*c], stats[2*c+1]), 0.f);
    }
    __syncthreads();
    for (int i = ly; i < 32; i += 8){
        float v = t[lx][i];
        __nv_bfloat16 h = __float2bfloat16(v);
        size_t o = ((size_t)(b * HW + hw0 + i)) * RS + co + c0 + lx;
        hi[o] = h;
        lo[o] = __float2bfloat16(v - __bfloat162float(h));
    }
}

// ---------------- weight prep ----------------
__global__ void wprep_kernel(const float* __restrict__ w,
                             __nv_bfloat16* __restrict__ hi,
                             __nv_bfloat16* __restrict__ lo,
                             int M, int C, int ntaps)
{
    int i = blockIdx.x * 256 + threadIdx.x;
    int Kt = ntaps * C;
    if (i < M * Kt){
        int m = i / Kt; int rest = i - m * Kt; int t = rest / C; int c = rest - t * C;
        float v = w[(size_t)(m * C + c) * ntaps + t];
        __nv_bfloat16 h = __float2bfloat16(v);
        hi[i] = h;
        lo[i] = __float2bfloat16(v - __bfloat162float(h));
    }
}

__global__ void wprep_qkv_kernel(const float* __restrict__ qw, const float* __restrict__ qb,
                                 const float* __restrict__ kw, const float* __restrict__ kb,
                                 const float* __restrict__ vw, const float* __restrict__ vb,
                                 __nv_bfloat16* __restrict__ hi, __nv_bfloat16* __restrict__ lo,
                                 float* __restrict__ bias)
{
    int i = blockIdx.x * 256 + threadIdx.x;
    if (i < QKVC * 256){
        int m = i >> 8, c = i & 255;
        float v = 0.f;
        if (m < 32)       v = qw[m * 256 + c];
        else if (m < 64)  v = kw[(m - 32) * 256 + c];
        else if (m < 320) v = vw[(m - 64) * 256 + c];
        __nv_bfloat16 h = __float2bfloat16(v);
        hi[i] = h;
        lo[i] = __float2bfloat16(v - __bfloat162float(h));
    }
    if (i < QKVC){
        float bv = 0.f;
        if (i < 32)       bv = qb[i];
        else if (i < 64)  bv = kb[i - 32];
        else if (i < 320) bv = vb[i - 64];
        bias[i] = bv;
    }
}

// ---------------- mma.sync implicit-GEMM conv (round-6 2-stage) ----------------
#define MC_SMEM (2*4*128*80)   // 81920

struct McCtx {
    const __nv_bfloat16 *Ahi, *Alo, *Bhi, *Blo;
    int C, ntaps, Ktot, cpT, RS, co;
    int r, half, b, yy, xx, am;
    uint32_t sb;
};

__device__ __forceinline__ void mc_load(const McCtx& cx, int cc, int buf)
{
    int t   = cc / cx.cpT;
    int ci0 = (cc - t * cx.cpT) << 5;
    uint32_t dst = cx.sb + buf * 40960 + cx.r * 80 + cx.half * 32;
    {
        size_t off = (size_t)cx.am * cx.Ktot + t * cx.C + ci0 + cx.half * 16;
        cp16(dst,              cx.Ahi + off,     16);
        cp16(dst + 16,         cx.Ahi + off + 8, 16);
        cp16(dst + 10240,      cx.Alo + off,     16);
        cp16(dst + 10240 + 16, cx.Alo + off + 8, 16);
    }
    {
        int dy = 0, dx = 0;
        if (cx.ntaps == 9){ dy = t / 3 - 1; dx = t - (t / 3) * 3 - 1; }
        int ys = cx.yy + dy, xs = cx.xx + dx;
        bool bv = (ys >= 0 && ys < HH && xs >= 0 && xs < WW);
        size_t off = bv ? ((size_t)(cx.b * HW + ys * WW + xs) * cx.RS + cx.co + ci0 + cx.half * 16) : 0;
        uint32_t sz = bv ? 16u : 0u;
        cp16(dst + 20480,      cx.Bhi + off,     sz);
        cp16(dst + 20480 + 16, cx.Bhi + off + 8, sz);
        cp16(dst + 30720,      cx.Blo + off,     sz);
        cp16(dst + 30720 + 16, cx.Blo + off + 8, sz);
    }
}

__global__ __launch_bounds__(256) void mma_conv_kernel(
    const __nv_bfloat16* __restrict__ Ahi, const __nv_bfloat16* __restrict__ Alo,
    const __nv_bfloat16* __restrict__ Bhi, const __nv_bfloat16* __restrict__ Blo,
    int M, int C, int ntaps, int RS, int co,
    const float* __restrict__ bias,
    float* __restrict__ out)
{
    extern __shared__ char dynsm[];
    const int tid = threadIdx.x, lane = tid & 31, wid = tid >> 5;
    const int wm = wid & 1, wn = wid >> 1;
    const int m0 = blockIdx.y * 128;
    const int n0 = blockIdx.x * 128;

    McCtx cx;
    cx.Ahi = Ahi; cx.Alo = Alo; cx.Bhi = Bhi; cx.Blo = Blo;
    cx.C = C; cx.ntaps = ntaps; cx.Ktot = ntaps * C; cx.cpT = C >> 5;
    cx.RS = RS; cx.co = co;
    cx.r = tid >> 1; cx.half = tid & 1;
    {
        int n = n0 + cx.r;
        cx.b = n / HW;
        int hw = n - cx.b * HW;
        cx.yy = hw / WW;
        cx.xx = hw - cx.yy * WW;
    }
    cx.am = m0 + cx.r;
    cx.sb = smem_u32(dynsm);

    float acc[4][4][4];
#pragma unroll
    for (int i = 0; i < 4; i++)
#pragma unroll
        for (int j = 0; j < 4; j++)
#pragma unroll
            for (int q = 0; q < 4; q++) acc[i][j][q] = 0.f;

    const int NC = cx.Ktot >> 5;

    mc_load(cx, 0, 0);
    asm volatile("cp.async.commit_group;" ::: "memory");

    const uint32_t aRowOff = (uint32_t)(lane & 15) * 80;
    const uint32_t aColOff = (uint32_t)(lane >> 4) * 16;
    const uint32_t bRowOff = (uint32_t)((lane & 7) + ((lane >> 4) << 3)) * 80;
    const uint32_t bColOff = (uint32_t)((lane >> 3) & 1) * 16;

    for (int cc = 0; cc < NC; cc++){
        int buf = cc & 1;
        if (cc + 1 < NC){
            mc_load(cx, cc + 1, (cc + 1) & 1);
            asm volatile("cp.async.commit_group;" ::: "memory");
            asm volatile("cp.async.wait_group 1;" ::: "memory");
        } else {
            asm volatile("cp.async.wait_group 0;" ::: "memory");
        }
        __syncthreads();
        uint32_t base = cx.sb + buf * 40960;
#pragma unroll
        for (int k16 = 0; k16 < 2; k16++){
            uint32_t ac = (uint32_t)k16 * 32 + aColOff;
            uint32_t bc = (uint32_t)k16 * 32 + bColOff;
            uint32_t ah[4][4], al[4][4], bh[2][4], bl[2][4];
#pragma unroll
            for (int mi = 0; mi < 4; mi++){
                uint32_t ad = base + (uint32_t)(wm * 64 + mi * 16) * 80 + aRowOff + ac;
                ldmx4(ah[mi], ad);
                ldmx4(al[mi], ad + 10240);
            }
#pragma unroll
            for (int ng = 0; ng < 2; ng++){
                uint32_t bd = base + 20480 + (uint32_t)(wn * 32 + ng * 16) * 80 + bRowOff + bc;
                ldmx4(bh[ng], bd);
                ldmx4(bl[ng], bd + 10240);
            }
#pragma unroll
            for (int mi = 0; mi < 4; mi++){
#pragma unroll
                for (int ni = 0; ni < 4; ni++){
                    const uint32_t* bhp = &bh[ni >> 1][(ni & 1) * 2];
                    const uint32_t* blp = &bl[ni >> 1][(ni & 1) * 2];
                    mma_bf16(acc[mi][ni], ah[mi], bhp);
                    mma_bf16(acc[mi][ni], ah[mi], blp);
                    mma_bf16(acc[mi][ni], al[mi], bhp);
                }
            }
        }
        __syncthreads();
    }

    int tb = n0 / HW;
    int hw0 = n0 - tb * HW;
#pragma unroll
    for (int mi = 0; mi < 4; mi++){
        int mrow = m0 + wm * 64 + mi * 16 + (lane >> 2);
        float b0 = bias ? __ldg(bias + mrow)     : 0.f;
        float b1 = bias ? __ldg(bias + mrow + 8) : 0.f;
#pragma unroll
        for (int ni = 0; ni < 4; ni++){
            int col = hw0 + wn * 32 + ni * 8 + (lane & 3) * 2;
            float2 v0 = make_float2(acc[mi][ni][0] + b0, acc[mi][ni][1] + b0);
            float2 v1 = make_float2(acc[mi][ni][2] + b1, acc[mi][ni][3] + b1);
            *(float2*)&out[((size_t)(tb * M + mrow)) * HW + col]     = v0;
            *(float2*)&out[((size_t)(tb * M + mrow + 8)) * HW + col] = v1;
        }
    }
}

// ---------------- fp32 GEMM (classifier only) ----------------
__global__ __launch_bounds__(256) void gemm_conv_kernel(
    const float* __restrict__ Wt, const float* __restrict__ p0,
    int M, int Cin, const float* __restrict__ bias, float* __restrict__ out)
{
    __shared__ float As[16][128];
    __shared__ float Bs[16][128];
    const int tid = threadIdx.x;
    const int tx = tid & 15, ty = tid >> 4;
    const int m0 = blockIdx.y * 128;
    const int n0 = blockIdx.x * 128;
    float acc[8][8];
#pragma unroll
    for (int i = 0; i < 8; i++)
#pragma unroll
        for (int j = 0; j < 8; j++) acc[i][j] = 0.f;
    const int nl = tid & 127;
    const int nglob = n0 + nl;
    const int bb = nglob / HW;
    const int hw = nglob - bb * HW;
    const int kbB = (tid >> 7) * 8;
    const int ml = tid >> 1;
    const int kbA = (tid & 1) * 8;
    for (int k0 = 0; k0 < Cin; k0 += 16){
        int m = m0 + ml;
        const float* wp = Wt + (size_t)m * Cin + (k0 + kbA);
#pragma unroll
        for (int i = 0; i < 8; i++)
            As[kbA + i][ml] = (m < M) ? wp[i] : 0.f;
#pragma unroll
        for (int i = 0; i < 8; i++)
            Bs[kbB + i][nl] = p0[((size_t)(bb * Cin + k0 + kbB + i)) * HW + hw];
        __syncthreads();
#pragma unroll
        for (int kk = 0; kk < 16; kk++){
            float a[8], bq[8];
#pragma unroll
            for (int i = 0; i < 8; i++) a[i]  = As[kk][ty + 16 * i];
#pragma unroll
            for (int j = 0; j < 8; j++) bq[j] = Bs[kk][tx + 16 * j];
#pragma unroll
            for (int i = 0; i < 8; i++)
#pragma unroll
                for (int j = 0; j < 8; j++)
                    acc[i][j] = fmaf(a[i], bq[j], acc[i][j]);
        }
        __syncthreads();
    }
#pragma unroll
    for (int i = 0; i < 8; i++){
        int m = m0 + ty + 16 * i;
        if (m >= M) continue;
        float bval = bias ? bias[m] : 0.f;
#pragma unroll
        for (int j = 0; j < 8; j++){
            int n = n0 + tx + 16 * j;
            int b = n / HW;
            int hw2 = n - b * HW;
            out[((size_t)(b * M + m)) * HW + hw2] = acc[i][j] + bval;
        }
    }
}

// ---------------- BatchNorm ----------------
__global__ void bn_stats_kernel(const float* __restrict__ x,
                                const float* __restrict__ g,
                                const float* __restrict__ bta,
                                float* __restrict__ stats, int C)
{
    int c = blockIdx.x, tid = threadIdx.x;
    float s = 0.f, sq = 0.f;
    for (int i = tid; i < NB * HW; i += 256){
        int bb = i / HW;
        float v = x[((size_t)(bb * C + c)) * HW + (i - bb * HW)];
        s += v; sq += v * v;
    }
    __shared__ float sh1[256], sh2[256];
    sh1[tid] = s; sh2[tid] = sq;
    __syncthreads();
    for (int st = 128; st; st >>= 1){
        if (tid < st){ sh1[tid] += sh1[tid + st]; sh2[tid] += sh2[tid + st]; }
        __syncthreads();
    }
    if (tid == 0){
        float n = (float)(NB * HW);
        float m = sh1[0] / n;
        float var = sh2[0] / n - m * m;
        float sc = g[c] * rsqrtf(var + 1e-5f);
        stats[2 * c] = sc;
        stats[2 * c + 1] = bta[c] - m * sc;
    }
}

__global__ void bn_apply_kernel(const float* __restrict__ x,
                                const float* __restrict__ stats,
                                float* __restrict__ y, int C, int total)
{
    int i = blockIdx.x * 256 + threadIdx.x;
    if (i < total){
        int c = (i / HW) % C;
        y[i] = fmaxf(fmaf(x[i], stats[2 * c], stats[2 * c + 1]), 0.f);
    }
}

// ---------------- criss-cross attention ----------------
__global__ void cc_logits_col_kernel(const float* __restrict__ qkv,
                                     float* __restrict__ att)
{
    int w = blockIdx.x, b = blockIdx.y, tid = threadIdx.x;
    __shared__ float qs[32][48], ks[32][48];
    for (int i = tid; i < 32 * 48; i += 256){
        int c = i / 48, h = i - (i / 48) * 48;
        qs[c][h] = qkv[((size_t)((b * QKVC + c) * 48 + h)) * 48 + w];
        ks[c][h] = qkv[((size_t)((b * QKVC + 32 + c) * 48 + h)) * 48 + w];
    }
    __syncthreads();
    for (int i = tid; i < 48 * 48; i += 256){
        int h = i / 48, g = i - (i / 48) * 48;
        float s;
        if (g == h) s = NEG_INF;
        else {
            s = 0.f;
#pragma unroll
            for (int c = 0; c < 32; c++) s += qs[c][h] * ks[c][g];
        }
        att[((size_t)((b * 48 + h) * 48 + w)) * 96 + g] = s;
    }
}

__global__ void cc_logits_row_kernel(const float* __restrict__ qkv,
                                     float* __restrict__ att)
{
    int h = blockIdx.x, b = blockIdx.y, tid = threadIdx.x;
    __shared__ float qs[32][48], ks[32][48];
    for (int i = tid; i < 32 * 48; i += 256){
        int c = i / 48, w = i - (i / 48) * 48;
        qs[c][w] = qkv[((size_t)((b * QKVC + c) * 48 + h)) * 48 + w];
        ks[c][w] = qkv[((size_t)((b * QKVC + 32 + c) * 48 + h)) * 48 + w];
    }
    __syncthreads();
    for (int i = tid; i < 48 * 48; i += 256){
        int w = i / 48, v2 = i - (i / 48) * 48;
        float s = 0.f;
#pragma unroll
        for (int c = 0; c < 32; c++) s += qs[c][w] * ks[c][v2];
        att[((size_t)((b * 48 + h) * 48 + w)) * 96 + 48 + v2] = s;
    }
}

__global__ void cc_softmax_kernel(float* __restrict__ att)
{
    int row  = blockIdx.x * 8 + (threadIdx.x >> 5);
    int lane = threadIdx.x & 31;
    float* p = att + (size_t)row * 96;
    float v0 = p[lane], v1 = p[lane + 32], v2 = p[lane + 64];
    float mx = fmaxf(v0, fmaxf(v1, v2));
#pragma unroll
    for (int off = 16; off; off >>= 1) mx = fmaxf(mx, __shfl_xor_sync(0xffffffff, mx, off));
    float e0 = expf(v0 - mx), e1 = expf(v1 - mx), e2 = expf(v2 - mx);
    float s = e0 + e1 + e2;
#pragma unroll
    for (int off = 16; off; off >>= 1) s += __shfl_xor_sync(0xffffffff, s, off);
    float inv = 1.f / s;
    p[lane] = e0 * inv; p[lane + 32] = e1 * inv; p[lane + 64] = e2 * inv;
}

#define CC_SMEM ((256*48 + 48*48) * 4)

__global__ void cc_out_col_kernel(const float* __restrict__ qkv,
                                  const float* __restrict__ att,
                                  const float* __restrict__ xin,
                                  const float* __restrict__ gamma,
                                  float* __restrict__ out)
{
    extern __shared__ float cs[];
    float* vs = cs; float* as = cs + 256 * 48;
    int w = blockIdx.x, b = blockIdx.y, tid = threadIdx.x;
    for (int i = tid; i < 256 * 48; i += 256){
        int c = i / 48, g = i - (i / 48) * 48;
        vs[i] = qkv[((size_t)((b * QKVC + 64 + c) * 48 + g)) * 48 + w];
    }
    for (int i = tid; i < 48 * 48; i += 256){
        int h = i / 48, g = i - (i / 48) * 48;
        as[i] = att[((size_t)((b * 48 + h) * 48 + w)) * 96 + g];
    }
    __syncthreads();
    float gm = gamma[0];
    for (int i = tid; i < 256 * 48; i += 256){
        int c = i / 48, h = i - (i / 48) * 48;
        float s = 0.f;
#pragma unroll
        for (int g = 0; g < 48; g++) s += vs[c * 48 + g] * as[h * 48 + g];
        size_t o = ((size_t)((b * 256 + c) * 48 + h)) * 48 + w;
        out[o] = xin[o] + gm * s;
    }
}

__global__ void cc_out_row_kernel(const float* __restrict__ qkv,
                                  const float* __restrict__ att,
                                  const float* __restrict__ gamma,
                                  float* __restrict__ out)
{
    extern __shared__ float cs[];
    float* vs = cs; float* as = cs + 256 * 48;
    int h = blockIdx.x, b = blockIdx.y, tid = threadIdx.x;
    for (int i = tid; i < 256 * 48; i += 256){
        vs[i] = qkv[((size_t)(b * QKVC + 64 + i / 48) * 48 + h) * 48 + (i % 48)];
    }
    for (int i = tid; i < 48 * 48; i += 256){
        int w2 = i / 48, v2 = i - (i / 48) * 48;
        as[i] = att[((size_t)((b * 48 + h) * 48 + w2)) * 96 + 48 + v2];
    }
    __syncthreads();
    float gm = gamma[0];
    for (int i = tid; i < 256 * 48; i += 256){
        int c = i / 48, w2 = i - (i / 48) * 48;
        float s = 0.f;
#pragma unroll
        for (int v2 = 0; v2 < 48; v2++) s += vs[c * 48 + v2] * as[w2 * 48 + v2];
        size_t o = ((size_t)((b * 256 + c) * 48 + h)) * 48 + w2;
        out[o] += gm * s;
    }
}

// ---------------- grid attention ----------------
__global__ void gram_kernel(const float* __restrict__ qkv,
                            float* __restrict__ S)
{
    int b1 = blockIdx.x >> 4, b2 = blockIdx.x & 15;
    const float* qp = qkv + (size_t)b1 * (QKVC * HW);
    const float* kp = qkv + (size_t)b2 * (QKVC * HW) + 32 * HW;
    int tid = threadIdx.x;
    float s = 0.f;
    for (int i = tid; i < C8 * HW; i += 256) s += qp[i] * kp[i];
    __shared__ float sh[256];
    sh[tid] = s;
    __syncthreads();
    for (int st = 128; st; st >>= 1){
        if (tid < st) sh[tid] += sh[tid + st];
        __syncthreads();
    }
    if (tid == 0) S[blockIdx.x] = sh[0];
}

__global__ void myw_kernel(const float* __restrict__ S, float* __restrict__ Wm)
{
    int b1 = threadIdx.x;
    if (b1 < 16){
        int gh = b1 >> 2, gw = b1 & 3;
        float l[8];
        for (int j = 0; j < 4; j++){
            int b2 = j * 4 + gw;
            l[j] = (j == gh) ? NEG_INF : S[b1 * 16 + b2];
        }
        for (int j = 0; j < 4; j++) l[4 + j] = S[b1 * 16 + gh * 4 + j];
        float mx = NEG_INF;
        for (int j = 0; j < 8; j++) mx = fmaxf(mx, l[j]);
        float sm = 0.f;
        for (int j = 0; j < 8; j++){ l[j] = expf(l[j] - mx); sm += l[j]; }
        float inv = 1.f / sm;
        float w[16];
        for (int i = 0; i < 16; i++) w[i] = 0.f;
        for (int j = 0; j < 4; j++) w[j * 4 + gw] += l[j] * inv;
        for (int j = 0; j < 4; j++) w[gh * 4 + j] += l[4 + j] * inv;
        for (int i = 0; i < 16; i++) Wm[b1 * 16 + i] = w[i];
    }
}

__global__ void my_combine_kernel(const float* __restrict__ qkv,
                                  const float* __restrict__ Wm,
                                  const float* __restrict__ xin,
                                  const float* __restrict__ gamma,
                                  float* __restrict__ out)
{
    __shared__ float ws[256];
    if (threadIdx.x < 256) ws[threadIdx.x] = Wm[threadIdx.x];
    __syncthreads();
    const int PB = CMID * HW;
    int n = blockIdx.x * 256 + threadIdx.x;
    if (n < PB){
        float vv[16];
#pragma unroll
        for (int b = 0; b < 16; b++)
            vv[b] = qkv[(size_t)b * (QKVC * HW) + 64 * HW + n];
        float gm = gamma[0];
#pragma unroll
        for (int b1 = 0; b1 < 16; b1++){
            float o = 0.f;
#pragma unroll
            for (int b2 = 0; b2 < 16; b2++) o += ws[b1 * 16 + b2] * vv[b2];
            out[(size_t)b1 * PB + n] = gm * o + xin[(size_t)b1 * PB + n];
        }
    }
}

// ---------------- host ----------------
extern "C" void kernel_launch(void* const* d_in, const int* in_sizes, int n_in,
                              void* d_out, int out_size)
{
    const float* x      = (const float*)d_in[0];
    const float* w_a    = (const float*)d_in[1];
    const float* g_a    = (const float*)d_in[2];
    const float* b_a    = (const float*)d_in[3];
    const float* ccq_w  = (const float*)d_in[4];
    const float* ccq_b  = (const float*)d_in[5];
    const float* cck_w  = (const float*)d_in[6];
    const float* cck_b  = (const float*)d_in[7];
    const float* ccv_w  = (const float*)d_in[8];
    const float* ccv_b  = (const float*)d_in[9];
    const float* cc_gm  = (const float*)d_in[10];
    const float* w_b    = (const float*)d_in[11];
    const float* g_b    = (const float*)d_in[12];
    const float* b_b    = (const float*)d_in[13];
    const float* w_m1   = (const float*)d_in[14];
    const float* g_m1   = (const float*)d_in[15];
    const float* b_m1   = (const float*)d_in[16];
    const float* myq_w  = (const float*)d_in[17];
    const float* myq_b  = (const float*)d_in[18];
    const float* myk_w  = (const float*)d_in[19];
    const float* myk_b  = (const float*)d_in[20];
    const float* myv_w  = (const float*)d_in[21];
    const float* myv_b  = (const float*)d_in[22];
    const float* my_gm  = (const float*)d_in[23];
    const float* w_m2   = (const float*)d_in[24];
    const float* g_m2   = (const float*)d_in[25];
    const float* b_m2   = (const float*)d_in[26];
    const float* w_c    = (const float*)d_in[27];
    const float* g_c    = (const float*)d_in[28];
    const float* b_c    = (const float*)d_in[29];
    const float* w_cls  = (const float*)d_in[30];
    const float* b_cls  = (const float*)d_in[31];

    cudaFuncSetAttribute(mma_conv_kernel, cudaFuncAttributeMaxDynamicSharedMemorySize, MC_SMEM);
    cudaFuncSetAttribute(cc_out_col_kernel, cudaFuncAttributeMaxDynamicSharedMemorySize, CC_SMEM);
    cudaFuncSetAttribute(cc_out_row_kernel, cudaFuncAttributeMaxDynamicSharedMemorySize, CC_SMEM);

    float *pt0, *pcc, *pmy, *pt1, *pqkv, *ph, *pst, *pS, *pWm, *patt, *pBcc, *pBmy;
    cudaGetSymbolAddress((void**)&pt0, g_t0);
    cudaGetSymbolAddress((void**)&pcc, g_cc);
    cudaGetSymbolAddress((void**)&pmy, g_my);
    cudaGetSymbolAddress((void**)&pt1, g_t1);
    cudaGetSymbolAddress((void**)&pqkv, g_qkv);
    cudaGetSymbolAddress((void**)&ph,  g_h);
    cudaGetSymbolAddress((void**)&pst, g_stats);
    cudaGetSymbolAddress((void**)&pS,  g_S);
    cudaGetSymbolAddress((void**)&pWm, g_Wm);
    cudaGetSymbolAddress((void**)&patt, g_att);
    cudaGetSymbolAddress((void**)&pBcc, g_Bcc);
    cudaGetSymbolAddress((void**)&pBmy, g_Bmy);

    __nv_bfloat16 *XCh,*XCl,*ACTh,*ACTl;
    __nv_bfloat16 *WAh,*WAl,*WM1h,*WM1l,*WBh,*WBl,*WM2h,*WM2l,*WCh,*WCl;
    __nv_bfloat16 *WQcch,*WQccl,*WQmyh,*WQmyl;
    cudaGetSymbolAddress((void**)&XCh, g_XCh);   cudaGetSymbolAddress((void**)&XCl, g_XCl);
    cudaGetSymbolAddress((void**)&ACTh, g_ACTh); cudaGetSymbolAddress((void**)&ACTl, g_ACTl);
    cudaGetSymbolAddress((void**)&WAh, g_WAh);   cudaGetSymbolAddress((void**)&WAl, g_WAl);
    cudaGetSymbolAddress((void**)&WM1h, g_WM1h); cudaGetSymbolAddress((void**)&WM1l, g_WM1l);
    cudaGetSymbolAddress((void**)&WBh, g_WBh);   cudaGetSymbolAddress((void**)&WBl, g_WBl);
    cudaGetSymbolAddress((void**)&WM2h, g_WM2h); cudaGetSymbolAddress((void**)&WM2l, g_WM2l);
    cudaGetSymbolAddress((void**)&WCh, g_WCh);   cudaGetSymbolAddress((void**)&WCl, g_WCl);
    cudaGetSymbolAddress((void**)&WQcch, g_WQcch); cudaGetSymbolAddress((void**)&WQccl, g_WQccl);
    cudaGetSymbolAddress((void**)&WQmyh, g_WQmyh); cudaGetSymbolAddress((void**)&WQmyl, g_WQmyl);

    const dim3 blk(256);
    const dim3 tr_blk(32, 8);
    const int NT = NTOT / 128;
    const int TOT_MID = NB*CMID*HW;

    // weight prep
    wprep_kernel<<<(256*9216 + 255)/256, blk>>>(w_a,  WAh,  WAl,  256, 1024, 9);
    wprep_kernel<<<(256*9216 + 255)/256, blk>>>(w_m1, WM1h, WM1l, 256, 1024, 9);
    wprep_kernel<<<(256*2304 + 255)/256, blk>>>(w_b,  WBh,  WBl,  256, 256, 9);
    wprep_kernel<<<(256*2304 + 255)/256, blk>>>(w_m2, WM2h, WM2l, 256, 256, 9);
    wprep_kernel<<<(512*13824 + 255)/256, blk>>>(w_c, WCh,  WCl,  512, 1536, 9);
    wprep_qkv_kernel<<<(QKVC*256 + 255)/256, blk>>>(ccq_w, ccq_b, cck_w, cck_b, ccv_w, ccv_b,
                                                    WQcch, WQccl, pBcc);
    wprep_qkv_kernel<<<(QKVC*256 + 255)/256, blk>>>(myq_w, myq_b, myk_w, myk_b, myv_w, myv_b,
                                                    WQmyh, WQmyl, pBmy);

    // x -> XC[0:1024]
    to_nhwc_kernel<<<dim3(HW/32, 1024/32, NB), tr_blk>>>(x, XCh, XCl, 1024, 1536, 0);

    // conv_a, conv_m1
    mma_conv_kernel<<<dim3(NT, 2), blk, MC_SMEM>>>(WAh, WAl, XCh, XCl, 256, 1024, 9, 1536, 0, nullptr, pt0);
    bn_stats_kernel<<<CMID, blk>>>(pt0, g_a, b_a, pst, CMID);
    bn_apply_kernel<<<(TOT_MID + 255)/256, blk>>>(pt0, pst, pcc, CMID, TOT_MID);

    mma_conv_kernel<<<dim3(NT, 2), blk, MC_SMEM>>>(WM1h, WM1l, XCh, XCl, 256, 1024, 9, 1536, 0, nullptr, pt0);
    bn_stats_kernel<<<CMID, blk>>>(pt0, g_m1, b_m1, pst, CMID);
    bn_apply_kernel<<<(TOT_MID + 255)/256, blk>>>(pt0, pst, pmy, CMID, TOT_MID);

    // cc attention x2
    {
        float* ca = pcc; float* cb = pt1;
        for (int it = 0; it < 2; it++){
            to_nhwc_kernel<<<dim3(HW/32, 256/32, NB), tr_blk>>>(ca, ACTh, ACTl, 256, 256, 0);
            mma_conv_kernel<<<dim3(NT, 3), blk, MC_SMEM>>>(WQcch, WQccl, ACTh, ACTl,
                                                           QKVC, 256, 1, 256, 0, pBcc, pqkv);
            cc_logits_col_kernel<<<dim3(WW, NB), blk>>>(pqkv, patt);
            cc_logits_row_kernel<<<dim3(HH, NB), blk>>>(pqkv, patt);
            cc_softmax_kernel<<<NTOT/8, blk>>>(patt);
            cc_out_col_kernel<<<dim3(WW, NB), blk, CC_SMEM>>>(pqkv, patt, ca, cc_gm, cb);
            cc_out_row_kernel<<<dim3(HH, NB), blk, CC_SMEM>>>(pqkv, patt, cc_gm, cb);
            float* tmp = ca; ca = cb; cb = tmp;
        }
    }

    // my attention x2
    {
        float* ma = pmy; float* mb = pt1;
        for (int it = 0; it < 2; it++){
            to_nhwc_kernel<<<dim3(HW/32, 256/32, NB), tr_blk>>>(ma, ACTh, ACTl, 256, 256, 0);
            mma_conv_kernel<<<dim3(NT, 3), blk, MC_SMEM>>>(WQmyh, WQmyl, ACTh, ACTl,
                                                           QKVC, 256, 1, 256, 0, pBmy, pqkv);
            gram_kernel<<<256, blk>>>(pqkv, pS);
            myw_kernel<<<1, 32>>>(pS, pWm);
            my_combine_kernel<<<(CMID*HW + 255)/256, blk>>>(pqkv, pWm, ma, my_gm, mb);
            float* tmp = ma; ma = mb; mb = tmp;
        }
    }

    // conv_b: input pcc -> BN -> XC@1024 (fused)
    to_nhwc_kernel<<<dim3(HW/32, 256/32, NB), tr_blk>>>(pcc, ACTh, ACTl, 256, 256, 0);
    mma_conv_kernel<<<dim3(NT, 2), blk, MC_SMEM>>>(WBh, WBl, ACTh, ACTl, 256, 256, 9, 256, 0, nullptr, pt0);
    bn_stats_kernel<<<CMID, blk>>>(pt0, g_b, b_b, pst, CMID);
    bn_to_nhwc_kernel<<<dim3(HW/32, 256/32, NB), tr_blk>>>(pt0, pst, XCh, XCl, 256, 1536, 1024);

    // conv_m2: input pmy -> BN -> XC@1280 (fused)
    to_nhwc_kernel<<<dim3(HW/32, 256/32, NB), tr_blk>>>(pmy, ACTh, ACTl, 256, 256, 0);
    mma_conv_kernel<<<dim3(NT, 2), blk, MC_SMEM>>>(WM2h, WM2l, ACTh, ACTl, 256, 256, 9, 256, 0, nullptr, pt0);
    bn_stats_kernel<<<CMID, blk>>>(pt0, g_m2, b_m2, pst, CMID);
    bn_to_nhwc_kernel<<<dim3(HW/32, 256/32, NB), tr_blk>>>(pt0, pst, XCh, XCl, 256, 1536, 1280);

    // conv_c + BN
    mma_conv_kernel<<<dim3(NT, 4), blk, MC_SMEM>>>(WCh, WCl, XCh, XCl, 512, 1536, 9, 1536, 0, nullptr, ph);
    bn_stats_kernel<<<OCH, blk>>>(ph, g_c, b_c, pst, OCH);
    bn_apply_kernel<<<(NB*OCH*HW + 255)/256, blk>>>(ph, pst, ph, OCH, NB*OCH*HW);

    // classifier
    gemm_conv_kernel<<<dim3(NT, 1), blk>>>(w_cls, ph, NCLS, OCH, b_cls, (float*)d_out);
}

// round 9
// speedup vs baseline: 1.6520x; 1.3954x over previous
#include <cuda_runtime.h>
#include <cuda_fp16.h>
#include <math.h>
#include <stdint.h>

#define NB   16
#define CIN  1024
#define CMID 256
#define C8   32
#define HH   48
#define WW   48
#define HW   (HH*WW)
#define NTOT (NB*HW)
#define OCH  512
#define NCLS 21
#define QKVC 384
#define NEG_INF (__int_as_float(0xff800000))

// ---------------- static scratch ----------------
__device__ float g_t0[NB*CMID*HW];
__device__ float g_cc[NB*CMID*HW];
__device__ float g_my[NB*CMID*HW];
__device__ float g_t1[NB*CMID*HW];
__device__ float g_qkv[(size_t)NB*QKVC*HW];
__device__ float g_h [NB*OCH*HW];
__device__ float g_stats[2*OCH];
__device__ float g_S[256];
__device__ float g_Wm[256];
__device__ float g_att[(size_t)NTOT*96];
__device__ float g_Bcc[QKVC];
__device__ float g_Bmy[QKVC];

__device__ __align__(256) __half g_XCh[(size_t)NTOT*1536];
__device__ __align__(256) __half g_XCl[(size_t)NTOT*1536];
__device__ __align__(256) __half g_ACTh[(size_t)NTOT*256];
__device__ __align__(256) __half g_ACTl[(size_t)NTOT*256];
__device__ __align__(256) __half g_WA [256*9216];
__device__ __align__(256) __half g_WM1[256*9216];
__device__ __align__(256) __half g_WB [256*2304];
__device__ __align__(256) __half g_WM2[256*2304];
__device__ __align__(256) __half g_WC [512*13824];
__device__ __align__(256) __half g_WQcc[QKVC*256];
__device__ __align__(256) __half g_WQmy[QKVC*256];

// ---------------- helpers ----------------
__device__ __forceinline__ uint32_t smem_u32(const void* p){
    uint32_t a;
    asm("{ .reg .u64 t; cvta.to.shared.u64 t, %1; cvt.u32.u64 %0, t; }" : "=r"(a) : "l"(p));
    return a;
}
__device__ __forceinline__ void cp16(uint32_t s, const void* g, uint32_t sz){
    asm volatile("cp.async.cg.shared.global [%0], [%1], 16, %2;" :: "r"(s), "l"(g), "r"(sz) : "memory");
}
__device__ __forceinline__ void ldmx4(uint32_t* r, uint32_t a){
    asm volatile("ldmatrix.sync.aligned.m8n8.x4.shared.b16 {%0,%1,%2,%3}, [%4];"
        : "=r"(r[0]),"=r"(r[1]),"=r"(r[2]),"=r"(r[3]) : "r"(a));
}
__device__ __forceinline__ void mma_f16(float* d, const uint32_t* a, const uint32_t* b){
    asm volatile("mma.sync.aligned.m16n8k16.row.col.f32.f16.f16.f32 "
        "{%0,%1,%2,%3}, {%4,%5,%6,%7}, {%8,%9}, {%0,%1,%2,%3};"
        : "+f"(d[0]),"+f"(d[1]),"+f"(d[2]),"+f"(d[3])
        : "r"(a[0]),"r"(a[1]),"r"(a[2]),"r"(a[3]), "r"(b[0]),"r"(b[1]));
}

// ---------------- NCHW fp32 -> NHWC fp16 hi/lo ----------------
__global__ void to_nhwc_kernel(const float* __restrict__ src,
                               __half* __restrict__ hi,
                               __half* __restrict__ lo,
                               int C, int RS, int co)
{
    __shared__ float t[32][33];
    int hw0 = blockIdx.x * 32, c0 = blockIdx.y * 32, b = blockIdx.z;
    int lx = threadIdx.x, ly = threadIdx.y;
    for (int i = ly; i < 32; i += 8)
        t[i][lx] = src[((size_t)(b * C + c0 + i)) * HW + hw0 + lx];
    __syncthreads();
    for (int i = ly; i < 32; i += 8){
        float v = t[lx][i];
        __half h = __float2half_rn(v);
        size_t o = ((size_t)(b * HW + hw0 + i)) * RS + co + c0 + lx;
        hi[o] = h;
        lo[o] = __float2half_rn(v - __half2float(h));
    }
}

__global__ void bn_to_nhwc_kernel(const float* __restrict__ src,
                                  const float* __restrict__ stats,
                                  __half* __restrict__ hi,
                                  __half* __restrict__ lo,
                                  int C, int RS, int co)
{
    __shared__ float t[32][33];
    int hw0 = blockIdx.x * 32, c0 = blockIdx.y * 32, b = blockIdx.z;
    int lx = threadIdx.x, ly = threadIdx.y;
    for (int i = ly; i < 32; i += 8){
        int c = c0 + i;
        float v = src[((size_t)(b * C + c)) * HW + hw0 + lx];
        t[i][lx] = fmaxf(fmaf(v, stats[2*c], stats[2*c+1]), 0.f);
    }
    __syncthreads();
    for (int i = ly; i < 32; i += 8){
        float v = t[lx][i];
        __half h = __float2half_rn(v);
        size_t o = ((size_t)(b * HW + hw0 + i)) * RS + co + c0 + lx;
        hi[o] = h;
        lo[o] = __float2half_rn(v - __half2float(h));
    }
}

// ---------------- weight prep (fp16 hi only) ----------------
__global__ void wprep_kernel(const float* __restrict__ w,
                             __half* __restrict__ hi,
                             int M, int C, int ntaps)
{
    int i = blockIdx.x * 256 + threadIdx.x;
    int Kt = ntaps * C;
    if (i < M * Kt){
        int m = i / Kt; int rest = i - m * Kt; int t = rest / C; int c = rest - t * C;
        hi[i] = __float2half_rn(w[(size_t)(m * C + c) * ntaps + t]);
    }
}

__global__ void wprep_qkv_kernel(const float* __restrict__ qw, const float* __restrict__ qb,
                                 const float* __restrict__ kw, const float* __restrict__ kb,
                                 const float* __restrict__ vw, const float* __restrict__ vb,
                                 __half* __restrict__ hi,
                                 float* __restrict__ bias)
{
    int i = blockIdx.x * 256 + threadIdx.x;
    if (i < QKVC * 256){
        int m = i >> 8, c = i & 255;
        float v = 0.f;
        if (m < 32)       v = qw[m * 256 + c];
        else if (m < 64)  v = kw[(m - 32) * 256 + c];
        else if (m < 320) v = vw[(m - 64) * 256 + c];
        hi[i] = __float2half_rn(v);
    }
    if (i < QKVC){
        float bv = 0.f;
        if (i < 32)       bv = qb[i];
        else if (i < 64)  bv = kb[i - 32];
        else if (i < 320) bv = vb[i - 64];
        bias[i] = bv;
    }
}

// ---------------- mma.sync implicit-GEMM conv (fp16 2-product) ----------------
// Smem per buffer: A-hi (128x80B) + B-hi + B-lo = 30720 B; 2 buffers.
#define MC_BUF  30720
#define MC_SMEM (2*MC_BUF)   // 61440

struct McCtx {
    const __half *A, *Bh, *Bl;
    int C, ntaps, Ktot, cpT, RS, co;
    int r, half, b, yy, xx, am;
    uint32_t sb;
};

__device__ __forceinline__ void mc_load(const McCtx& cx, int cc, int buf)
{
    int t   = cc / cx.cpT;
    int ci0 = (cc - t * cx.cpT) << 5;
    uint32_t dst = cx.sb + buf * MC_BUF + cx.r * 80 + cx.half * 32;
    {   // A hi only
        size_t off = (size_t)cx.am * cx.Ktot + t * cx.C + ci0 + cx.half * 16;
        cp16(dst,      cx.A + off,     16);
        cp16(dst + 16, cx.A + off + 8, 16);
    }
    {   // B hi + lo
        int dy = 0, dx = 0;
        if (cx.ntaps == 9){ dy = t / 3 - 1; dx = t - (t / 3) * 3 - 1; }
        int ys = cx.yy + dy, xs = cx.xx + dx;
        bool bv = (ys >= 0 && ys < HH && xs >= 0 && xs < WW);
        size_t off = bv ? ((size_t)(cx.b * HW + ys * WW + xs) * cx.RS + cx.co + ci0 + cx.half * 16) : 0;
        uint32_t sz = bv ? 16u : 0u;
        cp16(dst + 10240,      cx.Bh + off,     sz);
        cp16(dst + 10240 + 16, cx.Bh + off + 8, sz);
        cp16(dst + 20480,      cx.Bl + off,     sz);
        cp16(dst + 20480 + 16, cx.Bl + off + 8, sz);
    }
}

__global__ __launch_bounds__(256) void mma_conv_kernel(
    const __half* __restrict__ A,
    const __half* __restrict__ Bh, const __half* __restrict__ Bl,
    int M, int C, int ntaps, int RS, int co,
    const float* __restrict__ bias,
    float* __restrict__ out)
{
    extern __shared__ char dynsm[];
    const int tid = threadIdx.x, lane = tid & 31, wid = tid >> 5;
    const int wm = wid & 1, wn = wid >> 1;
    const int m0 = blockIdx.y * 128;
    const int n0 = blockIdx.x * 128;

    McCtx cx;
    cx.A = A; cx.Bh = Bh; cx.Bl = Bl;
    cx.C = C; cx.ntaps = ntaps; cx.Ktot = ntaps * C; cx.cpT = C >> 5;
    cx.RS = RS; cx.co = co;
    cx.r = tid >> 1; cx.half = tid & 1;
    {
        int n = n0 + cx.r;
        cx.b = n / HW;
        int hw = n - cx.b * HW;
        cx.yy = hw / WW;
        cx.xx = hw - cx.yy * WW;
    }
    cx.am = m0 + cx.r;
    cx.sb = smem_u32(dynsm);

    float acc[4][4][4];
#pragma unroll
    for (int i = 0; i < 4; i++)
#pragma unroll
        for (int j = 0; j < 4; j++)
#pragma unroll
            for (int q = 0; q < 4; q++) acc[i][j][q] = 0.f;

    const int NC = cx.Ktot >> 5;

    mc_load(cx, 0, 0);
    asm volatile("cp.async.commit_group;" ::: "memory");

    const uint32_t aRowOff = (uint32_t)(lane & 15) * 80;
    const uint32_t aColOff = (uint32_t)(lane >> 4) * 16;
    const uint32_t bRowOff = (uint32_t)((lane & 7) + ((lane >> 4) << 3)) * 80;
    const uint32_t bColOff = (uint32_t)((lane >> 3) & 1) * 16;

    for (int cc = 0; cc < NC; cc++){
        int buf = cc & 1;
        if (cc + 1 < NC){
            mc_load(cx, cc + 1, (cc + 1) & 1);
            asm volatile("cp.async.commit_group;" ::: "memory");
            asm volatile("cp.async.wait_group 1;" ::: "memory");
        } else {
            asm volatile("cp.async.wait_group 0;" ::: "memory");
        }
        __syncthreads();
        uint32_t base = cx.sb + buf * MC_BUF;
#pragma unroll
        for (int k16 = 0; k16 < 2; k16++){
            uint32_t ac = (uint32_t)k16 * 32 + aColOff;
            uint32_t bc = (uint32_t)k16 * 32 + bColOff;
            uint32_t ah[4][4], bh[2][4], bl[2][4];
#pragma unroll
            for (int mi = 0; mi < 4; mi++){
                uint32_t ad = base + (uint32_t)(wm * 64 + mi * 16) * 80 + aRowOff + ac;
                ldmx4(ah[mi], ad);
            }
#pragma unroll
            for (int ng = 0; ng < 2; ng++){
                uint32_t bd = base + 10240 + (uint32_t)(wn * 32 + ng * 16) * 80 + bRowOff + bc;
                ldmx4(bh[ng], bd);
                ldmx4(bl[ng], bd + 10240);
            }
#pragma unroll
            for (int mi = 0; mi < 4; mi++){
#pragma unroll
                for (int ni = 0; ni < 4; ni++){
                    const uint32_t* bhp = &bh[ni >> 1][(ni & 1) * 2];
                    const uint32_t* blp = &bl[ni >> 1][(ni & 1) * 2];
                    mma_f16(acc[mi][ni], ah[mi], bhp);
                    mma_f16(acc[mi][ni], ah[mi], blp);
                }
            }
        }
        __syncthreads();
    }

    int tb = n0 / HW;
    int hw0 = n0 - tb * HW;
#pragma unroll
    for (int mi = 0; mi < 4; mi++){
        int mrow = m0 + wm * 64 + mi * 16 + (lane >> 2);
        float b0 = bias ? __ldg(bias + mrow)     : 0.f;
        float b1 = bias ? __ldg(bias + mrow + 8) : 0.f;
#pragma unroll
        for (int ni = 0; ni < 4; ni++){
            int col = hw0 + wn * 32 + ni * 8 + (lane & 3) * 2;
            float2 v0 = make_float2(acc[mi][ni][0] + b0, acc[mi][ni][1] + b0);
            float2 v1 = make_float2(acc[mi][ni][2] + b1, acc[mi][ni][3] + b1);
            *(float2*)&out[((size_t)(tb * M + mrow)) * HW + col]     = v0;
            *(float2*)&out[((size_t)(tb * M + mrow + 8)) * HW + col] = v1;
        }
    }
}

// ---------------- fp32 GEMM (classifier only) ----------------
__global__ __launch_bounds__(256) void gemm_conv_kernel(
    const float* __restrict__ Wt, const float* __restrict__ p0,
    int M, int Cin, const float* __restrict__ bias, float* __restrict__ out)
{
    __shared__ float As[16][128];
    __shared__ float Bs[16][128];
    const int tid = threadIdx.x;
    const int tx = tid & 15, ty = tid >> 4;
    const int m0 = blockIdx.y * 128;
    const int n0 = blockIdx.x * 128;
    float acc[8][8];
#pragma unroll
    for (int i = 0; i < 8; i++)
#pragma unroll
        for (int j = 0; j < 8; j++) acc[i][j] = 0.f;
    const int nl = tid & 127;
    const int nglob = n0 + nl;
    const int bb = nglob / HW;
    const int hw = nglob - bb * HW;
    const int kbB = (tid >> 7) * 8;
    const int ml = tid >> 1;
    const int kbA = (tid & 1) * 8;
    for (int k0 = 0; k0 < Cin; k0 += 16){
        int m = m0 + ml;
        const float* wp = Wt + (size_t)m * Cin + (k0 + kbA);
#pragma unroll
        for (int i = 0; i < 8; i++)
            As[kbA + i][ml] = (m < M) ? wp[i] : 0.f;
#pragma unroll
        for (int i = 0; i < 8; i++)
            Bs[kbB + i][nl] = p0[((size_t)(bb * Cin + k0 + kbB + i)) * HW + hw];
        __syncthreads();
#pragma unroll
        for (int kk = 0; kk < 16; kk++){
            float a[8], bq[8];
#pragma unroll
            for (int i = 0; i < 8; i++) a[i]  = As[kk][ty + 16 * i];
#pragma unroll
            for (int j = 0; j < 8; j++) bq[j] = Bs[kk][tx + 16 * j];
#pragma unroll
            for (int i = 0; i < 8; i++)
#pragma unroll
                for (int j = 0; j < 8; j++)
                    acc[i][j] = fmaf(a[i], bq[j], acc[i][j]);
        }
        __syncthreads();
    }
#pragma unroll
    for (int i = 0; i < 8; i++){
        int m = m0 + ty + 16 * i;
        if (m >= M) continue;
        float bval = bias ? bias[m] : 0.f;
#pragma unroll
        for (int j = 0; j < 8; j++){
            int n = n0 + tx + 16 * j;
            int b = n / HW;
            int hw2 = n - b * HW;
            out[((size_t)(b * M + m)) * HW + hw2] = acc[i][j] + bval;
        }
    }
}

// ---------------- BatchNorm ----------------
__global__ void bn_stats_kernel(const float* __restrict__ x,
                                const float* __restrict__ g,
                                const float* __restrict__ bta,
                                float* __restrict__ stats, int C)
{
    int c = blockIdx.x, tid = threadIdx.x;
    float s = 0.f, sq = 0.f;
    for (int i = tid; i < NB * HW; i += 256){
        int bb = i / HW;
        float v = x[((size_t)(bb * C + c)) * HW + (i - bb * HW)];
        s += v; sq += v * v;
    }
    __shared__ float sh1[256], sh2[256];
    sh1[tid] = s; sh2[tid] = sq;
    __syncthreads();
    for (int st = 128; st; st >>= 1){
        if (tid < st){ sh1[tid] += sh1[tid + st]; sh2[tid] += sh2[tid + st]; }
        __syncthreads();
    }
    if (tid == 0){
        float n = (float)(NB * HW);
        float m = sh1[0] / n;
        float var = sh2[0] / n - m * m;
        float sc = g[c] * rsqrtf(var + 1e-5f);
        stats[2 * c] = sc;
        stats[2 * c + 1] = bta[c] - m * sc;
    }
}

__global__ void bn_apply_kernel(const float* __restrict__ x,
                                const float* __restrict__ stats,
                                float* __restrict__ y, int C, int total)
{
    int i = blockIdx.x * 256 + threadIdx.x;
    if (i < total){
        int c = (i / HW) % C;
        y[i] = fmaxf(fmaf(x[i], stats[2 * c], stats[2 * c + 1]), 0.f);
    }
}

// ---------------- criss-cross attention ----------------
__global__ void cc_logits_col_kernel(const float* __restrict__ qkv,
                                     float* __restrict__ att)
{
    int w = blockIdx.x, b = blockIdx.y, tid = threadIdx.x;
    __shared__ float qs[32][48], ks[32][48];
    for (int i = tid; i < 32 * 48; i += 256){
        int c = i / 48, h = i - (i / 48) * 48;
        qs[c][h] = qkv[((size_t)((b * QKVC + c) * 48 + h)) * 48 + w];
        ks[c][h] = qkv[((size_t)((b * QKVC + 32 + c) * 48 + h)) * 48 + w];
    }
    __syncthreads();
    for (int i = tid; i < 48 * 48; i += 256){
        int h = i / 48, g = i - (i / 48) * 48;
        float s;
        if (g == h) s = NEG_INF;
        else {
            s = 0.f;
#pragma unroll
            for (int c = 0; c < 32; c++) s += qs[c][h] * ks[c][g];
        }
        att[((size_t)((b * 48 + h) * 48 + w)) * 96 + g] = s;
    }
}

__global__ void cc_logits_row_kernel(const float* __restrict__ qkv,
                                     float* __restrict__ att)
{
    int h = blockIdx.x, b = blockIdx.y, tid = threadIdx.x;
    __shared__ float qs[32][48], ks[32][48];
    for (int i = tid; i < 32 * 48; i += 256){
        int c = i / 48, w = i - (i / 48) * 48;
        qs[c][w] = qkv[((size_t)((b * QKVC + c) * 48 + h)) * 48 + w];
        ks[c][w] = qkv[((size_t)((b * QKVC + 32 + c) * 48 + h)) * 48 + w];
    }
    __syncthreads();
    for (int i = tid; i < 48 * 48; i += 256){
        int w = i / 48, v2 = i - (i / 48) * 48;
        float s = 0.f;
#pragma unroll
        for (int c = 0; c < 32; c++) s += qs[c][w] * ks[c][v2];
        att[((size_t)((b * 48 + h) * 48 + w)) * 96 + 48 + v2] = s;
    }
}

__global__ void cc_softmax_kernel(float* __restrict__ att)
{
    int row  = blockIdx.x * 8 + (threadIdx.x >> 5);
    int lane = threadIdx.x & 31;
    float* p = att + (size_t)row * 96;
    float v0 = p[lane], v1 = p[lane + 32], v2 = p[lane + 64];
    float mx = fmaxf(v0, fmaxf(v1, v2));
#pragma unroll
    for (int off = 16; off; off >>= 1) mx = fmaxf(mx, __shfl_xor_sync(0xffffffff, mx, off));
    float e0 = expf(v0 - mx), e1 = expf(v1 - mx), e2 = expf(v2 - mx);
    float s = e0 + e1 + e2;
#pragma unroll
    for (int off = 16; off; off >>= 1) s += __shfl_xor_sync(0xffffffff, s, off);
    float inv = 1.f / s;
    p[lane] = e0 * inv; p[lane + 32] = e1 * inv; p[lane + 64] = e2 * inv;
}

#define CC_SMEM ((256*48 + 48*48) * 4)

__global__ void cc_out_col_kernel(const float* __restrict__ qkv,
                                  const float* __restrict__ att,
                                  const float* __restrict__ xin,
                                  const float* __restrict__ gamma,
                                  float* __restrict__ out)
{
    extern __shared__ float cs[];
    float* vs = cs; float* as = cs + 256 * 48;
    int w = blockIdx.x, b = blockIdx.y, tid = threadIdx.x;
    for (int i = tid; i < 256 * 48; i += 256){
        int c = i / 48, g = i - (i / 48) * 48;
        vs[i] = qkv[((size_t)((b * QKVC + 64 + c) * 48 + g)) * 48 + w];
    }
    for (int i = tid; i < 48 * 48; i += 256){
        int h = i / 48, g = i - (i / 48) * 48;
        as[i] = att[((size_t)((b * 48 + h) * 48 + w)) * 96 + g];
    }
    __syncthreads();
    float gm = gamma[0];
    for (int i = tid; i < 256 * 48; i += 256){
        int c = i / 48, h = i - (i / 48) * 48;
        float s = 0.f;
#pragma unroll
        for (int g = 0; g < 48; g++) s += vs[c * 48 + g] * as[h * 48 + g];
        size_t o = ((size_t)((b * 256 + c) * 48 + h)) * 48 + w;
        out[o] = xin[o] + gm * s;
    }
}

__global__ void cc_out_row_kernel(const float* __restrict__ qkv,
                                  const float* __restrict__ att,
                                  const float* __restrict__ gamma,
                                  float* __restrict__ out)
{
    extern __shared__ float cs[];
    float* vs = cs; float* as = cs + 256 * 48;
    int h = blockIdx.x, b = blockIdx.y, tid = threadIdx.x;
    for (int i = tid; i < 256 * 48; i += 256){
        vs[i] = qkv[((size_t)(b * QKVC + 64 + i / 48) * 48 + h) * 48 + (i % 48)];
    }
    for (int i = tid; i < 48 * 48; i += 256){
        int w2 = i / 48, v2 = i - (i / 48) * 48;
        as[i] = att[((size_t)((b * 48 + h) * 48 + w2)) * 96 + 48 + v2];
    }
    __syncthreads();
    float gm = gamma[0];
    for (int i = tid; i < 256 * 48; i += 256){
        int c = i / 48, w2 = i - (i / 48) * 48;
        float s = 0.f;
#pragma unroll
        for (int v2 = 0; v2 < 48; v2++) s += vs[c * 48 + v2] * as[w2 * 48 + v2];
        size_t o = ((size_t)((b * 256 + c) * 48 + h)) * 48 + w2;
        out[o] += gm * s;
    }
}

// ---------------- grid attention ----------------
__global__ void gram_kernel(const float* __restrict__ qkv,
                            float* __restrict__ S)
{
    int b1 = blockIdx.x >> 4, b2 = blockIdx.x & 15;
    const float* qp = qkv + (size_t)b1 * (QKVC * HW);
    const float* kp = qkv + (size_t)b2 * (QKVC * HW) + 32 * HW;
    int tid = threadIdx.x;
    float s = 0.f;
    for (int i = tid; i < C8 * HW; i += 256) s += qp[i] * kp[i];
    __shared__ float sh[256];
    sh[tid] = s;
    __syncthreads();
    for (int st = 128; st; st >>= 1){
        if (tid < st) sh[tid] += sh[tid + st];
        __syncthreads();
    }
    if (tid == 0) S[blockIdx.x] = sh[0];
}

__global__ void myw_kernel(const float* __restrict__ S, float* __restrict__ Wm)
{
    int b1 = threadIdx.x;
    if (b1 < 16){
        int gh = b1 >> 2, gw = b1 & 3;
        float l[8];
        for (int j = 0; j < 4; j++){
            int b2 = j * 4 + gw;
            l[j] = (j == gh) ? NEG_INF : S[b1 * 16 + b2];
        }
        for (int j = 0; j < 4; j++) l[4 + j] = S[b1 * 16 + gh * 4 + j];
        float mx = NEG_INF;
        for (int j = 0; j < 8; j++) mx = fmaxf(mx, l[j]);
        float sm = 0.f;
        for (int j = 0; j < 8; j++){ l[j] = expf(l[j] - mx); sm += l[j]; }
        float inv = 1.f / sm;
        float w[16];
        for (int i = 0; i < 16; i++) w[i] = 0.f;
        for (int j = 0; j < 4; j++) w[j * 4 + gw] += l[j] * inv;
        for (int j = 0; j < 4; j++) w[gh * 4 + j] += l[4 + j] * inv;
        for (int i = 0; i < 16; i++) Wm[b1 * 16 + i] = w[i];
    }
}

__global__ void my_combine_kernel(const float* __restrict__ qkv,
                                  const float* __restrict__ Wm,
                                  const float* __restrict__ xin,
                                  const float* __restrict__ gamma,
                                  float* __restrict__ out)
{
    __shared__ float ws[256];
    if (threadIdx.x < 256) ws[threadIdx.x] = Wm[threadIdx.x];
    __syncthreads();
    const int PB = CMID * HW;
    int n = blockIdx.x * 256 + threadIdx.x;
    if (n < PB){
        float vv[16];
#pragma unroll
        for (int b = 0; b < 16; b++)
            vv[b] = qkv[(size_t)b * (QKVC * HW) + 64 * HW + n];
        float gm = gamma[0];
#pragma unroll
        for (int b1 = 0; b1 < 16; b1++){
            float o = 0.f;
#pragma unroll
            for (int b2 = 0; b2 < 16; b2++) o += ws[b1 * 16 + b2] * vv[b2];
            out[(size_t)b1 * PB + n] = gm * o + xin[(size_t)b1 * PB + n];
        }
    }
}

// ---------------- host ----------------
extern "C" void kernel_launch(void* const* d_in, const int* in_sizes, int n_in,
                              void* d_out, int out_size)
{
    const float* x      = (const float*)d_in[0];
    const float* w_a    = (const float*)d_in[1];
    const float* g_a    = (const float*)d_in[2];
    const float* b_a    = (const float*)d_in[3];
    const float* ccq_w  = (const float*)d_in[4];
    const float* ccq_b  = (const float*)d_in[5];
    const float* cck_w  = (const float*)d_in[6];
    const float* cck_b  = (const float*)d_in[7];
    const float* ccv_w  = (const float*)d_in[8];
    const float* ccv_b  = (const float*)d_in[9];
    const float* cc_gm  = (const float*)d_in[10];
    const float* w_b    = (const float*)d_in[11];
    const float* g_b    = (const float*)d_in[12];
    const float* b_b    = (const float*)d_in[13];
    const float* w_m1   = (const float*)d_in[14];
    const float* g_m1   = (const float*)d_in[15];
    const float* b_m1   = (const float*)d_in[16];
    const float* myq_w  = (const float*)d_in[17];
    const float* myq_b  = (const float*)d_in[18];
    const float* myk_w  = (const float*)d_in[19];
    const float* myk_b  = (const float*)d_in[20];
    const float* myv_w  = (const float*)d_in[21];
    const float* myv_b  = (const float*)d_in[22];
    const float* my_gm  = (const float*)d_in[23];
    const float* w_m2   = (const float*)d_in[24];
    const float* g_m2   = (const float*)d_in[25];
    const float* b_m2   = (const float*)d_in[26];
    const float* w_c    = (const float*)d_in[27];
    const float* g_c    = (const float*)d_in[28];
    const float* b_c    = (const float*)d_in[29];
    const float* w_cls  = (const float*)d_in[30];
    const float* b_cls  = (const float*)d_in[31];

    cudaFuncSetAttribute(mma_conv_kernel, cudaFuncAttributeMaxDynamicSharedMemorySize, MC_SMEM);
    cudaFuncSetAttribute(cc_out_col_kernel, cudaFuncAttributeMaxDynamicSharedMemorySize, CC_SMEM);
    cudaFuncSetAttribute(cc_out_row_kernel, cudaFuncAttributeMaxDynamicSharedMemorySize, CC_SMEM);

    float *pt0, *pcc, *pmy, *pt1, *pqkv, *ph, *pst, *pS, *pWm, *patt, *pBcc, *pBmy;
    cudaGetSymbolAddress((void**)&pt0, g_t0);
    cudaGetSymbolAddress((void**)&pcc, g_cc);
    cudaGetSymbolAddress((void**)&pmy, g_my);
    cudaGetSymbolAddress((void**)&pt1, g_t1);
    cudaGetSymbolAddress((void**)&pqkv, g_qkv);
    cudaGetSymbolAddress((void**)&ph,  g_h);
    cudaGetSymbolAddress((void**)&pst, g_stats);
    cudaGetSymbolAddress((void**)&pS,  g_S);
    cudaGetSymbolAddress((void**)&pWm, g_Wm);
    cudaGetSymbolAddress((void**)&patt, g_att);
    cudaGetSymbolAddress((void**)&pBcc, g_Bcc);
    cudaGetSymbolAddress((void**)&pBmy, g_Bmy);

    __half *XCh,*XCl,*ACTh,*ACTl;
    __half *WA,*WM1,*WB,*WM2,*WC,*WQcc,*WQmy;
    cudaGetSymbolAddress((void**)&XCh, g_XCh);   cudaGetSymbolAddress((void**)&XCl, g_XCl);
    cudaGetSymbolAddress((void**)&ACTh, g_ACTh); cudaGetSymbolAddress((void**)&ACTl, g_ACTl);
    cudaGetSymbolAddress((void**)&WA, g_WA);
    cudaGetSymbolAddress((void**)&WM1, g_WM1);
    cudaGetSymbolAddress((void**)&WB, g_WB);
    cudaGetSymbolAddress((void**)&WM2, g_WM2);
    cudaGetSymbolAddress((void**)&WC, g_WC);
    cudaGetSymbolAddress((void**)&WQcc, g_WQcc);
    cudaGetSymbolAddress((void**)&WQmy, g_WQmy);

    const dim3 blk(256);
    const dim3 tr_blk(32, 8);
    const int NT = NTOT / 128;
    const int TOT_MID = NB*CMID*HW;

    // weight prep
    wprep_kernel<<<(256*9216 + 255)/256, blk>>>(w_a,  WA,  256, 1024, 9);
    wprep_kernel<<<(256*9216 + 255)/256, blk>>>(w_m1, WM1, 256, 1024, 9);
    wprep_kernel<<<(256*2304 + 255)/256, blk>>>(w_b,  WB,  256, 256, 9);
    wprep_kernel<<<(256*2304 + 255)/256, blk>>>(w_m2, WM2, 256, 256, 9);
    wprep_kernel<<<(512*13824 + 255)/256, blk>>>(w_c, WC,  512, 1536, 9);
    wprep_qkv_kernel<<<(QKVC*256 + 255)/256, blk>>>(ccq_w, ccq_b, cck_w, cck_b, ccv_w, ccv_b,
                                                    WQcc, pBcc);
    wprep_qkv_kernel<<<(QKVC*256 + 255)/256, blk>>>(myq_w, myq_b, myk_w, myk_b, myv_w, myv_b,
                                                    WQmy, pBmy);

    // x -> XC[0:1024]
    to_nhwc_kernel<<<dim3(HW/32, 1024/32, NB), tr_blk>>>(x, XCh, XCl, 1024, 1536, 0);

    // conv_a, conv_m1
    mma_conv_kernel<<<dim3(NT, 2), blk, MC_SMEM>>>(WA, XCh, XCl, 256, 1024, 9, 1536, 0, nullptr, pt0);
    bn_stats_kernel<<<CMID, blk>>>(pt0, g_a, b_a, pst, CMID);
    bn_apply_kernel<<<(TOT_MID + 255)/256, blk>>>(pt0, pst, pcc, CMID, TOT_MID);

    mma_conv_kernel<<<dim3(NT, 2), blk, MC_SMEM>>>(WM1, XCh, XCl, 256, 1024, 9, 1536, 0, nullptr, pt0);
    bn_stats_kernel<<<CMID, blk>>>(pt0, g_m1, b_m1, pst, CMID);
    bn_apply_kernel<<<(TOT_MID + 255)/256, blk>>>(pt0, pst, pmy, CMID, TOT_MID);

    // cc attention x2
    {
        float* ca = pcc; float* cb = pt1;
        for (int it = 0; it < 2; it++){
            to_nhwc_kernel<<<dim3(HW/32, 256/32, NB), tr_blk>>>(ca, ACTh, ACTl, 256, 256, 0);
            mma_conv_kernel<<<dim3(NT, 3), blk, MC_SMEM>>>(WQcc, ACTh, ACTl,
                                                           QKVC, 256, 1, 256, 0, pBcc, pqkv);
            cc_logits_col_kernel<<<dim3(WW, NB), blk>>>(pqkv, patt);
            cc_logits_row_kernel<<<dim3(HH, NB), blk>>>(pqkv, patt);
            cc_softmax_kernel<<<NTOT/8, blk>>>(patt);
            cc_out_col_kernel<<<dim3(WW, NB), blk, CC_SMEM>>>(pqkv, patt, ca, cc_gm, cb);
            cc_out_row_kernel<<<dim3(HH, NB), blk, CC_SMEM>>>(pqkv, patt, cc_gm, cb);
            float* tmp = ca; ca = cb; cb = tmp;
        }
    }

    // my attention x2
    {
        float* ma = pmy; float* mb = pt1;
        for (int it = 0; it < 2; it++){
            to_nhwc_kernel<<<dim3(HW/32, 256/32, NB), tr_blk>>>(ma, ACTh, ACTl, 256, 256, 0);
            mma_conv_kernel<<<dim3(NT, 3), blk, MC_SMEM>>>(WQmy, ACTh, ACTl,
                                                           QKVC, 256, 1, 256, 0, pBmy, pqkv);
            gram_kernel<<<256, blk>>>(pqkv, pS);
            myw_kernel<<<1, 32>>>(pS, pWm);
            my_combine_kernel<<<(CMID*HW + 255)/256, blk>>>(pqkv, pWm, ma, my_gm, mb);
            float* tmp = ma; ma = mb; mb = tmp;
        }
    }

    // conv_b: input pcc -> BN -> XC@1024 (fused)
    to_nhwc_kernel<<<dim3(HW/32, 256/32, NB), tr_blk>>>(pcc, ACTh, ACTl, 256, 256, 0);
    mma_conv_kernel<<<dim3(NT, 2), blk, MC_SMEM>>>(WB, ACTh, ACTl, 256, 256, 9, 256, 0, nullptr, pt0);
    bn_stats_kernel<<<CMID, blk>>>(pt0, g_b, b_b, pst, CMID);
    bn_to_nhwc_kernel<<<dim3(HW/32, 256/32, NB), tr_blk>>>(pt0, pst, XCh, XCl, 256, 1536, 1024);

    // conv_m2: input pmy -> BN -> XC@1280 (fused)
    to_nhwc_kernel<<<dim3(HW/32, 256/32, NB), tr_blk>>>(pmy, ACTh, ACTl, 256, 256, 0);
    mma_conv_kernel<<<dim3(NT, 2), blk, MC_SMEM>>>(WM2, ACTh, ACTl, 256, 256, 9, 256, 0, nullptr, pt0);
    bn_stats_kernel<<<CMID, blk>>>(pt0, g_m2, b_m2, pst, CMID);
    bn_to_nhwc_kernel<<<dim3(HW/32, 256/32, NB), tr_blk>>>(pt0, pst, XCh, XCl, 256, 1536, 1280);

    // conv_c + BN
    mma_conv_kernel<<<dim3(NT, 4), blk, MC_SMEM>>>(WC, XCh, XCl, 512, 1536, 9, 1536, 0, nullptr, ph);
    bn_stats_kernel<<<OCH, blk>>>(ph, g_c, b_c, pst, OCH);
    bn_apply_kernel<<<(NB*OCH*HW + 255)/256, blk>>>(ph, pst, ph, OCH, NB*OCH*HW);

    // classifier
    gemm_conv_kernel<<<dim3(NT, 1), blk>>>(w_cls, ph, NCLS, OCH, b_cls, (float*)d_out);
}